// round 13
// baseline (speedup 1.0000x reference)
#include <cuda_runtime.h>
#include <cuda_fp16.h>
#include <mma.h>

using namespace nvcuda;

#define N_NODES  100000
#define N_EDGES  1600000
#define N_GRAPHS 512
#define IN_DIM   64
#define HID      128

#define SCAN_B   1024
#define SCAN_NB  ((N_NODES + SCAN_B - 1) / SCAN_B)   // 98
#define EQ4      (N_EDGES / 4)                        // 400000 int4 quads
#define FB       ((EQ4 + 255) / 256)                  // 1563 fill blocks
#define PB       ((N_NODES * (IN_DIM / 2)) / 256)     // 12500 prep blocks

// ---------------- device scratch ----------------
// RULE (R3/R6): referenced ONLY inside device code; never passed as kernel
// arguments from host (host shadow address + HMM = silent corruption or
// memory-guard trips).
__device__ int    g_deg_in[N_NODES];
__device__ int    g_deg_out[N_NODES];
__device__ int    g_row_ptr[N_NODES];
__device__ int    g_cursor[N_NODES];
__device__ int    g_csr_src[N_EDGES];
__device__ float  g_rin[N_NODES];
__device__ float  g_rout[N_NODES];
__device__ __half g_xh[(size_t)N_NODES * IN_DIM];   // half(x * rout)
__device__ __half g_h1h[(size_t)N_NODES * HID];     // half(h1s)
__device__ __half g_aggh[(size_t)N_NODES * HID];    // half(agg) - GEMM A operand
__device__ float  g_pool[N_GRAPHS * HID];
__device__ int    g_gcnt[N_GRAPHS];
// single-pass scan state (re-zeroed by k_zero each call)
__device__ volatile int g_ssum[SCAN_NB];
__device__ volatile int g_sflag[SCAN_NB];

// go=0: degenerate warmup launch (forces lazy function load, touches nothing).

__global__ void k_zero(int go) {
    if (!go) return;
    int i = blockIdx.x * blockDim.x + threadIdx.x;
    if (i < N_NODES) { g_deg_in[i] = 0; g_deg_out[i] = 0; }
    if (i < N_GRAPHS * HID) g_pool[i] = 0.f;
    if (i < N_GRAPHS) g_gcnt[i] = 0;
    if (i < SCAN_NB) { g_sflag[i] = 0; g_ssum[i] = 0; }
}

// degree count, 4 edges per thread (int4 loads)
__global__ void k_deg4(int go, const int4* __restrict__ src4, const int4* __restrict__ dst4) {
    if (!go) return;
    int q = blockIdx.x * blockDim.x + threadIdx.x;
    if (q >= EQ4) return;
    int4 s = src4[q];
    int4 d = dst4[q];
    atomicAdd(&g_deg_out[s.x], 1); atomicAdd(&g_deg_out[s.y], 1);
    atomicAdd(&g_deg_out[s.z], 1); atomicAdd(&g_deg_out[s.w], 1);
    atomicAdd(&g_deg_in[d.x], 1);  atomicAdd(&g_deg_in[d.y], 1);
    atomicAdd(&g_deg_in[d.z], 1);  atomicAdd(&g_deg_in[d.w], 1);
}

// single-pass scan + CSR pointers + norms. 98 co-resident blocks -> lookback safe.
__global__ void k_scan(int go, const int* __restrict__ gids) {
    if (!go) return;
    __shared__ int s[SCAN_B];
    __shared__ int s_prefix;
    int b = blockIdx.x;
    int i = b * SCAN_B + threadIdx.x;
    int v = (i < N_NODES) ? g_deg_in[i] : 0;
    s[threadIdx.x] = v;
    __syncthreads();
    for (int off = 1; off < SCAN_B; off <<= 1) {
        int t = (threadIdx.x >= off) ? s[threadIdx.x - off] : 0;
        __syncthreads();
        s[threadIdx.x] += t;
        __syncthreads();
    }
    int incl = s[threadIdx.x];
    if (threadIdx.x == SCAN_B - 1) {
        g_ssum[b] = s[SCAN_B - 1];
        __threadfence();
        g_sflag[b] = 1;
    }
    if (threadIdx.x < 32) {
        int acc = 0;
        for (int j = threadIdx.x; j < b; j += 32) {
            while (g_sflag[j] == 0) { }
            acc += g_ssum[j];
        }
#pragma unroll
        for (int o = 16; o > 0; o >>= 1)
            acc += __shfl_down_sync(0xffffffffu, acc, o);
        if (threadIdx.x == 0) s_prefix = acc;
    }
    __syncthreads();
    if (i < N_NODES) {
        int din = v;
        int rp = incl - din + s_prefix;
        g_row_ptr[i] = rp;
        g_cursor[i]  = rp;
        g_rin[i]  = rsqrtf((float)max(din, 1));
        g_rout[i] = rsqrtf((float)max(g_deg_out[i], 1));
        atomicAdd(&g_gcnt[gids[i]], 1);
    }
}

// fused: CSR bucket fill (4 edges/thread) + g_xh = half(x * rout)
__global__ void k_fillprep(int go, const int4* __restrict__ src4,
                           const int4* __restrict__ dst4,
                           const float* __restrict__ x) {
    if (!go) return;
    int b = blockIdx.x;
    if (b < FB) {
        int q = b * blockDim.x + threadIdx.x;
        if (q >= EQ4) return;
        int4 s = src4[q];
        int4 d = dst4[q];
        g_csr_src[atomicAdd(&g_cursor[d.x], 1)] = s.x;
        g_csr_src[atomicAdd(&g_cursor[d.y], 1)] = s.y;
        g_csr_src[atomicAdd(&g_cursor[d.z], 1)] = s.z;
        g_csr_src[atomicAdd(&g_cursor[d.w], 1)] = s.w;
    } else {
        int i = (b - FB) * blockDim.x + threadIdx.x;   // half2 slot over N*64
        if (i >= N_NODES * (IN_DIM / 2)) return;
        int node = i / (IN_DIM / 2);
        float r = g_rout[node];
        float2 v = ((const float2*)x)[i];
        ((__half2*)g_xh)[i] = __floats2half2_rn(v.x * r, v.y * r);
    }
}

// layer-1 gather, 4-way edge split: lane = sub*8 + dl; each sub-warp of 8
// lanes covers all 64 halves via uint4 (8 halves/lane); 4 edges in flight.
__global__ void k_agg1h(int go) {
    if (!go) return;
    int warp = (blockIdx.x * blockDim.x + threadIdx.x) >> 5;
    if (warp >= N_NODES) return;
    int lane = threadIdx.x & 31;
    int sub = lane >> 3;          // 0..3: 4 edges per iteration
    int dl  = lane & 7;           // 8 lanes x 8 halves = 64
    int start = g_row_ptr[warp];
    int deg   = g_deg_in[warp];
    float a[8];
#pragma unroll
    for (int k = 0; k < 8; k++) a[k] = 0.f;
#pragma unroll 2
    for (int e = sub; e < deg; e += 4) {
        int src = g_csr_src[start + e];
        uint4 u = *(const uint4*)(g_xh + (size_t)src * IN_DIM + dl * 8);
        float2 f0 = __half22float2(*(const __half2*)&u.x);
        float2 f1 = __half22float2(*(const __half2*)&u.y);
        float2 f2 = __half22float2(*(const __half2*)&u.z);
        float2 f3 = __half22float2(*(const __half2*)&u.w);
        a[0] += f0.x; a[1] += f0.y; a[2] += f1.x; a[3] += f1.y;
        a[4] += f2.x; a[5] += f2.y; a[6] += f3.x; a[7] += f3.y;
    }
    // reduce over sub-warps: offset 16 folds sub{2,3} into {0,1}; 8 folds 1 into 0
#pragma unroll
    for (int k = 0; k < 8; k++) {
        a[k] += __shfl_down_sync(0xffffffffu, a[k], 16);
        a[k] += __shfl_down_sync(0xffffffffu, a[k], 8);
    }
    if (sub == 0) {
        float r = g_rin[warp];
        uint4 o;
        *(__half2*)&o.x = __floats2half2_rn(a[0] * r, a[1] * r);
        *(__half2*)&o.y = __floats2half2_rn(a[2] * r, a[3] * r);
        *(__half2*)&o.z = __floats2half2_rn(a[4] * r, a[5] * r);
        *(__half2*)&o.w = __floats2half2_rn(a[6] * r, a[7] * r);
        *(uint4*)(g_aggh + (size_t)warp * IN_DIM + dl * 8) = o;
    }
}

// layer-2 gather, 2 warps per node: warp pair {2k, 2k+1} splits the edge list,
// each covering all 128 halves (uint2/lane); partials merged via smem.
__global__ void k_agg2h(int go) {
    if (!go) return;
    __shared__ float red[4][HID];                 // odd-warp partials (4 nodes/block)
    int gw = (blockIdx.x * blockDim.x + threadIdx.x) >> 5;
    int node = gw >> 1;
    int half = gw & 1;
    int nslot = (threadIdx.x >> 5) >> 1;          // 0..3
    int lane = threadIdx.x & 31;
    float a0 = 0.f, a1 = 0.f, a2 = 0.f, a3 = 0.f;
    if (node < N_NODES) {
        int start = g_row_ptr[node];
        int deg   = g_deg_in[node];
#pragma unroll 4
        for (int e = half; e < deg; e += 2) {
            int src = g_csr_src[start + e];
            uint2 u = *(const uint2*)(g_h1h + (size_t)src * HID + lane * 4);
            float2 f0 = __half22float2(*(const __half2*)&u.x);
            float2 f1 = __half22float2(*(const __half2*)&u.y);
            a0 += f0.x; a1 += f0.y; a2 += f1.x; a3 += f1.y;
        }
    }
    if (half == 1) {                               // conflict-free: [k*32+lane]
        red[nslot][0 * 32 + lane] = a0;
        red[nslot][1 * 32 + lane] = a1;
        red[nslot][2 * 32 + lane] = a2;
        red[nslot][3 * 32 + lane] = a3;
    }
    __syncthreads();
    if (half == 0 && node < N_NODES) {
        a0 += red[nslot][0 * 32 + lane];
        a1 += red[nslot][1 * 32 + lane];
        a2 += red[nslot][2 * 32 + lane];
        a3 += red[nslot][3 * 32 + lane];
        float r = g_rin[node];
        uint2 o;
        *(__half2*)&o.x = __floats2half2_rn(a0 * r, a1 * r);
        *(__half2*)&o.y = __floats2half2_rn(a2 * r, a3 * r);
        *(uint2*)(g_aggh + (size_t)node * HID + lane * 4) = o;
    }
}

// C = relu(g_aggh[M,K] @ W[K,128] + b)
// fp16 MMA (m16n16k16) with W split into Wh + Wl halves -> ~fp32 W precision.
// OUTH=true : *= rout, write fp16 to g_h1h  (layer 1)
// OUTH=false: pooled epilogue — accumulate relu rows into g_pool by gid
template<int K, bool OUTH>
__global__ __launch_bounds__(256) void k_gemm_h(int go,
                                                const float* __restrict__ W,
                                                const float* __restrict__ bias,
                                                const int* __restrict__ gids) {
    if (!go) return;
    constexpr int BM = 64, BN = 128, BK = 16;
    constexpr int ALD  = BK + 8;   // halves
    constexpr int WLDH = BN + 8;   // halves
    constexpr int CLD  = BN + 4;   // floats
    constexpr int AB_BYTES = (BM * ALD + 2 * BK * WLDH) * 2;
    constexpr int C_BYTES  = BM * CLD * 4;
    constexpr int SM_BYTES = (AB_BYTES > C_BYTES) ? AB_BYTES : C_BYTES;
    __shared__ __align__(16) char smem_raw[SM_BYTES];
    __half* Ah = (__half*)smem_raw;               // [BM][ALD]
    __half* Wh = Ah + BM * ALD;                   // [BK][WLDH]
    __half* Wl = Wh + BK * WLDH;                  // [BK][WLDH]
    float*  Cs = (float*)smem_raw;                // [BM][CLD] (epilogue)

    int tid = threadIdx.x;
    int warp = tid >> 5;
    int wm = warp >> 2;
    int wn = warp & 3;
    int m0 = blockIdx.x * BM;

    wmma::fragment<wmma::accumulator, 16, 16, 16, float> acc[2][2];
#pragma unroll
    for (int i = 0; i < 2; i++)
#pragma unroll
        for (int j = 0; j < 2; j++) wmma::fill_fragment(acc[i][j], 0.f);

    for (int k0 = 0; k0 < K; k0 += BK) {
        {
            int row = tid >> 2, c4 = tid & 3;
            int gm = m0 + row;
            uint2 v = make_uint2(0u, 0u);
            if (gm < N_NODES) v = *(const uint2*)(g_aggh + (size_t)gm * K + k0 + c4 * 4);
            *(uint2*)&Ah[row * ALD + c4 * 4] = v;
        }
#pragma unroll
        for (int l = 0; l < 2; l++) {
            int idx = tid + l * 256;
            int r = idx >> 5, c4 = idx & 31;
            float4 w = *(const float4*)(W + (size_t)(k0 + r) * BN + c4 * 4);
            __half2 h01 = __floats2half2_rn(w.x, w.y);
            __half2 h23 = __floats2half2_rn(w.z, w.w);
            float2 f01 = __half22float2(h01);
            float2 f23 = __half22float2(h23);
            __half2 l01 = __floats2half2_rn(w.x - f01.x, w.y - f01.y);
            __half2 l23 = __floats2half2_rn(w.z - f23.x, w.w - f23.y);
            uint2 hh, ll;
            *(__half2*)&hh.x = h01; *(__half2*)&hh.y = h23;
            *(__half2*)&ll.x = l01; *(__half2*)&ll.y = l23;
            *(uint2*)&Wh[r * WLDH + c4 * 4] = hh;
            *(uint2*)&Wl[r * WLDH + c4 * 4] = ll;
        }
        __syncthreads();

        wmma::fragment<wmma::matrix_a, 16, 16, 16, __half, wmma::row_major> a[2];
        wmma::fragment<wmma::matrix_b, 16, 16, 16, __half, wmma::row_major> bh[2], bl[2];
#pragma unroll
        for (int i = 0; i < 2; i++)
            wmma::load_matrix_sync(a[i], &Ah[(wm * 32 + i * 16) * ALD], ALD);
#pragma unroll
        for (int j = 0; j < 2; j++) {
            wmma::load_matrix_sync(bh[j], &Wh[wn * 32 + j * 16], WLDH);
            wmma::load_matrix_sync(bl[j], &Wl[wn * 32 + j * 16], WLDH);
        }
#pragma unroll
        for (int i = 0; i < 2; i++)
#pragma unroll
            for (int j = 0; j < 2; j++) {
                wmma::mma_sync(acc[i][j], a[i], bh[j], acc[i][j]);
                wmma::mma_sync(acc[i][j], a[i], bl[j], acc[i][j]);
            }
        __syncthreads();
    }

#pragma unroll
    for (int i = 0; i < 2; i++)
#pragma unroll
        for (int j = 0; j < 2; j++)
            wmma::store_matrix_sync(&Cs[(wm * 32 + i * 16) * CLD + wn * 32 + j * 16],
                                    acc[i][j], CLD, wmma::mem_row_major);
    __syncthreads();

    if (OUTH) {
        int row = tid >> 2, seg = tid & 3;
        int gm = m0 + row;
        if (gm < N_NODES) {
            float r = g_rout[gm];
#pragma unroll
            for (int q = 0; q < 8; q++) {
                int col = seg * 32 + q * 4;
                float4 v = *(float4*)&Cs[row * CLD + col];
                uint2 u;
                *(__half2*)&u.x = __floats2half2_rn(fmaxf(v.x + bias[col + 0], 0.f) * r,
                                                    fmaxf(v.y + bias[col + 1], 0.f) * r);
                *(__half2*)&u.y = __floats2half2_rn(fmaxf(v.z + bias[col + 2], 0.f) * r,
                                                    fmaxf(v.w + bias[col + 3], 0.f) * r);
                *(uint2*)(g_h1h + (size_t)gm * BN + col) = u;
            }
        }
    } else {
        int col = tid & 127;
        int r0 = (tid >> 7) * 32;
        float bcol = bias[col];
        int nrows = min(BM, N_NODES - m0);
        int lim = min(r0 + 32, nrows);
        if (r0 < nrows) {
            float acc_p = 0.f;
            int pg = gids[m0 + r0];
            for (int r = r0; r < lim; r++) {
                int g = gids[m0 + r];
                if (g != pg) {
                    atomicAdd(&g_pool[pg * HID + col], acc_p);
                    acc_p = 0.f;
                    pg = g;
                }
                acc_p += fmaxf(Cs[r * CLD + col] + bcol, 0.f);
            }
            atomicAdd(&g_pool[pg * HID + col], acc_p);
        }
    }
}

// MLP head: one block per graph
__global__ void k_head(int go,
                       const float* __restrict__ Wc1, const float* __restrict__ bc1,
                       const float* __restrict__ Wc2, const float* __restrict__ bc2,
                       const float* __restrict__ Wc3, const float* __restrict__ bc3,
                       float* __restrict__ out) {
    if (!go) return;
    __shared__ float s0[HID];
    __shared__ float s1[HID];
    int g = blockIdx.x, t = threadIdx.x;
    float cnt = fmaxf((float)g_gcnt[g], 1.f);
    s0[t] = g_pool[g * HID + t] / cnt;
    __syncthreads();
    float a = bc1[t];
#pragma unroll 8
    for (int k = 0; k < HID; k++) a = fmaf(s0[k], Wc1[k * HID + t], a);
    s1[t] = fmaxf(a, 0.f);
    __syncthreads();
    float b = bc2[t];
#pragma unroll 8
    for (int k = 0; k < HID; k++) b = fmaf(s1[k], Wc2[k * HID + t], b);
    float v = fmaxf(b, 0.f);
    __syncthreads();
    s1[t] = v * Wc3[t];
    __syncthreads();
    for (int off = 64; off > 0; off >>= 1) {
        if (t < off) s1[t] += s1[t + off];
        __syncthreads();
    }
    if (t == 0) out[g] = s1[0] + bc3[0];
}

// ---------------- eager module loader ----------------
namespace {
struct EagerLoad {
    EagerLoad() {
        int ndev = 0;
        if (cudaGetDeviceCount(&ndev) != cudaSuccess || ndev <= 0) return;
        for (int d = 0; d < ndev; d++) {
            if (cudaSetDevice(d) != cudaSuccess) continue;
            void* p;
            if (cudaGetSymbolAddress(&p, g_deg_in)  == cudaSuccess) cudaMemset(p, 0, sizeof(g_deg_in));
            if (cudaGetSymbolAddress(&p, g_deg_out) == cudaSuccess) cudaMemset(p, 0, sizeof(g_deg_out));
            if (cudaGetSymbolAddress(&p, g_row_ptr) == cudaSuccess) cudaMemset(p, 0, sizeof(g_row_ptr));
            if (cudaGetSymbolAddress(&p, g_cursor)  == cudaSuccess) cudaMemset(p, 0, sizeof(g_cursor));
            if (cudaGetSymbolAddress(&p, g_csr_src) == cudaSuccess) cudaMemset(p, 0, sizeof(g_csr_src));
            if (cudaGetSymbolAddress(&p, g_rin)     == cudaSuccess) cudaMemset(p, 0, sizeof(g_rin));
            if (cudaGetSymbolAddress(&p, g_rout)    == cudaSuccess) cudaMemset(p, 0, sizeof(g_rout));
            if (cudaGetSymbolAddress(&p, g_xh)      == cudaSuccess) cudaMemset(p, 0, sizeof(g_xh));
            if (cudaGetSymbolAddress(&p, g_h1h)     == cudaSuccess) cudaMemset(p, 0, sizeof(g_h1h));
            if (cudaGetSymbolAddress(&p, g_aggh)    == cudaSuccess) cudaMemset(p, 0, sizeof(g_aggh));
            if (cudaGetSymbolAddress(&p, g_pool)    == cudaSuccess) cudaMemset(p, 0, sizeof(g_pool));
            if (cudaGetSymbolAddress(&p, g_gcnt)    == cudaSuccess) cudaMemset(p, 0, sizeof(g_gcnt));
            if (cudaGetSymbolAddress(&p, (const void*)g_ssum)  == cudaSuccess) cudaMemset(p, 0, SCAN_NB * 4);
            if (cudaGetSymbolAddress(&p, (const void*)g_sflag) == cudaSuccess) cudaMemset(p, 0, SCAN_NB * 4);

            k_zero<<<1, 32>>>(0);
            k_deg4<<<1, 32>>>(0, nullptr, nullptr);
            k_scan<<<1, SCAN_B>>>(0, nullptr);
            k_fillprep<<<1, 256>>>(0, nullptr, nullptr, nullptr);
            k_agg1h<<<1, 32>>>(0);
            k_agg2h<<<1, 256>>>(0);
            k_gemm_h<IN_DIM, true><<<1, 256>>>(0, nullptr, nullptr, nullptr);
            k_gemm_h<HID, false><<<1, 256>>>(0, nullptr, nullptr, nullptr);
            k_head<<<1, HID>>>(0, nullptr, nullptr, nullptr, nullptr, nullptr, nullptr, nullptr);
            cudaDeviceSynchronize();
        }
        cudaSetDevice(0);
        cudaGetLastError();
    }
};
static EagerLoad _eager_load_instance;
}

// ---------------- launch ----------------
// Only harness-provided pointers cross the host/device argument boundary.
extern "C" void kernel_launch(void* const* d_in, const int* in_sizes, int n_in,
                              void* d_out, int out_size) {
    const float* x    = (const float*)d_in[0];
    const int*   esrc = (const int*)d_in[1];
    const int*   edst = (const int*)d_in[2];
    const int*   gids = (const int*)d_in[3];
    const float* W1 = (const float*)d_in[4];
    const float* b1 = (const float*)d_in[5];
    const float* W2 = (const float*)d_in[6];
    const float* b2 = (const float*)d_in[7];
    const float* Wc1 = (const float*)d_in[8];
    const float* bc1 = (const float*)d_in[9];
    const float* Wc2 = (const float*)d_in[10];
    const float* bc2 = (const float*)d_in[11];
    const float* Wc3 = (const float*)d_in[12];
    const float* bc3 = (const float*)d_in[13];
    float* out = (float*)d_out;

    const int GB  = (N_NODES + 63) / 64;
    const int AB1 = (N_NODES * 32 + 255) / 256;        // 1 warp/node
    const int AB2 = (N_NODES * 64 + 255) / 256;        // 2 warps/node

    k_zero<<<(N_NODES + 255) / 256, 256>>>(1);
    k_deg4<<<(EQ4 + 255) / 256, 256>>>(1, (const int4*)esrc, (const int4*)edst);
    k_scan<<<SCAN_NB, SCAN_B>>>(1, gids);
    k_fillprep<<<FB + PB, 256>>>(1, (const int4*)esrc, (const int4*)edst, x);

    // layer 1: h1s(fp16) = relu(rin*gather(half(x*rout)) @ W1 + b1) * rout
    k_agg1h<<<AB1, 256>>>(1);
    k_gemm_h<IN_DIM, true><<<GB, 256>>>(1, W1, b1, nullptr);

    // layer 2: gather + GEMM + fused mean-pool numerator (h2 never hits gmem)
    k_agg2h<<<AB2, 256>>>(1);
    k_gemm_h<HID, false><<<GB, 256>>>(1, W2, b2, gids);

    // MLP head
    k_head<<<N_GRAPHS, HID>>>(1, Wc1, bc1, Wc2, bc2, Wc3, bc3, out);
}

// round 14
// speedup vs baseline: 1.0159x; 1.0159x over previous
#include <cuda_runtime.h>
#include <cuda_fp16.h>
#include <mma.h>

using namespace nvcuda;

#define N_NODES  100000
#define N_EDGES  1600000
#define N_GRAPHS 512
#define IN_DIM   64
#define HID      128

#define SCAN_B   1024
#define SCAN_NB  ((N_NODES + SCAN_B - 1) / SCAN_B)   // 98
#define EQ4      (N_EDGES / 4)                        // 400000 int4 quads
#define FB       ((EQ4 + 255) / 256)                  // 1563 fill blocks
#define PB       ((N_NODES * (IN_DIM / 2)) / 256)     // 12500 prep blocks

// ---------------- device scratch ----------------
// RULE (R3/R6): referenced ONLY inside device code; never passed as kernel
// arguments from host (host shadow address + HMM = silent corruption or
// memory-guard trips).
__device__ int    g_deg_in[N_NODES];
__device__ int    g_deg_out[N_NODES];
__device__ int    g_row_ptr[N_NODES];
__device__ int    g_cursor[N_NODES];
__device__ int    g_csr_src[N_EDGES];
__device__ float  g_rin[N_NODES];
__device__ float  g_rout[N_NODES];
__device__ __half g_xh[(size_t)N_NODES * IN_DIM];   // half(x * rout)
__device__ __half g_h1h[(size_t)N_NODES * HID];     // half(h1s)
__device__ __half g_aggh[(size_t)N_NODES * HID];    // half(agg) - GEMM A operand
__device__ float  g_pool[N_GRAPHS * HID];
__device__ int    g_gcnt[N_GRAPHS];
// single-pass scan state (re-zeroed by k_zero each call)
__device__ volatile int g_ssum[SCAN_NB];
__device__ volatile int g_sflag[SCAN_NB];

// go=0: degenerate warmup launch (forces lazy function load, touches nothing).

__global__ void k_zero(int go) {
    if (!go) return;
    int i = blockIdx.x * blockDim.x + threadIdx.x;
    if (i < N_NODES) { g_deg_in[i] = 0; g_deg_out[i] = 0; }
    if (i < N_GRAPHS * HID) g_pool[i] = 0.f;
    if (i < N_GRAPHS) g_gcnt[i] = 0;
    if (i < SCAN_NB) { g_sflag[i] = 0; g_ssum[i] = 0; }
}

// degree count, 4 edges per thread (int4 loads)
__global__ void k_deg4(int go, const int4* __restrict__ src4, const int4* __restrict__ dst4) {
    if (!go) return;
    int q = blockIdx.x * blockDim.x + threadIdx.x;
    if (q >= EQ4) return;
    int4 s = src4[q];
    int4 d = dst4[q];
    atomicAdd(&g_deg_out[s.x], 1); atomicAdd(&g_deg_out[s.y], 1);
    atomicAdd(&g_deg_out[s.z], 1); atomicAdd(&g_deg_out[s.w], 1);
    atomicAdd(&g_deg_in[d.x], 1);  atomicAdd(&g_deg_in[d.y], 1);
    atomicAdd(&g_deg_in[d.z], 1);  atomicAdd(&g_deg_in[d.w], 1);
}

// single-pass scan + CSR pointers + norms. 98 co-resident blocks -> lookback safe.
__global__ void k_scan(int go, const int* __restrict__ gids) {
    if (!go) return;
    __shared__ int s[SCAN_B];
    __shared__ int s_prefix;
    int b = blockIdx.x;
    int i = b * SCAN_B + threadIdx.x;
    int v = (i < N_NODES) ? g_deg_in[i] : 0;
    s[threadIdx.x] = v;
    __syncthreads();
    for (int off = 1; off < SCAN_B; off <<= 1) {
        int t = (threadIdx.x >= off) ? s[threadIdx.x - off] : 0;
        __syncthreads();
        s[threadIdx.x] += t;
        __syncthreads();
    }
    int incl = s[threadIdx.x];
    if (threadIdx.x == SCAN_B - 1) {
        g_ssum[b] = s[SCAN_B - 1];
        __threadfence();
        g_sflag[b] = 1;
    }
    if (threadIdx.x < 32) {
        int acc = 0;
        for (int j = threadIdx.x; j < b; j += 32) {
            while (g_sflag[j] == 0) { }
            acc += g_ssum[j];
        }
#pragma unroll
        for (int o = 16; o > 0; o >>= 1)
            acc += __shfl_down_sync(0xffffffffu, acc, o);
        if (threadIdx.x == 0) s_prefix = acc;
    }
    __syncthreads();
    if (i < N_NODES) {
        int din = v;
        int rp = incl - din + s_prefix;
        g_row_ptr[i] = rp;
        g_cursor[i]  = rp;
        g_rin[i]  = rsqrtf((float)max(din, 1));
        g_rout[i] = rsqrtf((float)max(g_deg_out[i], 1));
        atomicAdd(&g_gcnt[gids[i]], 1);
    }
}

// fused: CSR bucket fill (4 edges/thread) + g_xh = half(x * rout)
__global__ void k_fillprep(int go, const int4* __restrict__ src4,
                           const int4* __restrict__ dst4,
                           const float* __restrict__ x) {
    if (!go) return;
    int b = blockIdx.x;
    if (b < FB) {
        int q = b * blockDim.x + threadIdx.x;
        if (q >= EQ4) return;
        int4 s = src4[q];
        int4 d = dst4[q];
        g_csr_src[atomicAdd(&g_cursor[d.x], 1)] = s.x;
        g_csr_src[atomicAdd(&g_cursor[d.y], 1)] = s.y;
        g_csr_src[atomicAdd(&g_cursor[d.z], 1)] = s.z;
        g_csr_src[atomicAdd(&g_cursor[d.w], 1)] = s.w;
    } else {
        int i = (b - FB) * blockDim.x + threadIdx.x;   // half2 slot over N*64
        if (i >= N_NODES * (IN_DIM / 2)) return;
        int node = i / (IN_DIM / 2);
        float r = g_rout[node];
        float2 v = ((const float2*)x)[i];
        ((__half2*)g_xh)[i] = __floats2half2_rn(v.x * r, v.y * r);
    }
}

// layer-1 gather (R12 form): 2-way edge split, 16 dim-lanes x 4 halves
__global__ void k_agg1h(int go) {
    if (!go) return;
    int warp = (blockIdx.x * blockDim.x + threadIdx.x) >> 5;
    if (warp >= N_NODES) return;
    int lane = threadIdx.x & 31;
    int sub = lane >> 4;          // 2 edges per iteration
    int dl  = lane & 15;          // 16 lanes x 4 halves = 64
    int start = g_row_ptr[warp];
    int deg   = g_deg_in[warp];
    float a0 = 0.f, a1 = 0.f, a2 = 0.f, a3 = 0.f;
#pragma unroll 4
    for (int e = sub; e < deg; e += 2) {
        int src = g_csr_src[start + e];
        uint2 u = *(const uint2*)(g_xh + (size_t)src * IN_DIM + dl * 4);
        float2 f0 = __half22float2(*(const __half2*)&u.x);
        float2 f1 = __half22float2(*(const __half2*)&u.y);
        a0 += f0.x; a1 += f0.y; a2 += f1.x; a3 += f1.y;
    }
    a0 += __shfl_down_sync(0xffffffffu, a0, 16);
    a1 += __shfl_down_sync(0xffffffffu, a1, 16);
    a2 += __shfl_down_sync(0xffffffffu, a2, 16);
    a3 += __shfl_down_sync(0xffffffffu, a3, 16);
    if (sub == 0) {
        float r = g_rin[warp];
        uint2 o;
        *(__half2*)&o.x = __floats2half2_rn(a0 * r, a1 * r);
        *(__half2*)&o.y = __floats2half2_rn(a2 * r, a3 * r);
        *(uint2*)(g_aggh + (size_t)warp * IN_DIM + dl * 4) = o;
    }
}

// layer-2 gather (R12 form): 1 warp/node, unroll 8
__global__ void k_agg2h(int go) {
    if (!go) return;
    int warp = (blockIdx.x * blockDim.x + threadIdx.x) >> 5;
    if (warp >= N_NODES) return;
    int lane = threadIdx.x & 31;  // 32 lanes x 4 halves = 128
    int start = g_row_ptr[warp];
    int deg   = g_deg_in[warp];
    float a0 = 0.f, a1 = 0.f, a2 = 0.f, a3 = 0.f;
#pragma unroll 8
    for (int e = 0; e < deg; e++) {
        int src = g_csr_src[start + e];
        uint2 u = *(const uint2*)(g_h1h + (size_t)src * HID + lane * 4);
        float2 f0 = __half22float2(*(const __half2*)&u.x);
        float2 f1 = __half22float2(*(const __half2*)&u.y);
        a0 += f0.x; a1 += f0.y; a2 += f1.x; a3 += f1.y;
    }
    float r = g_rin[warp];
    uint2 o;
    *(__half2*)&o.x = __floats2half2_rn(a0 * r, a1 * r);
    *(__half2*)&o.y = __floats2half2_rn(a2 * r, a3 * r);
    *(uint2*)(g_aggh + (size_t)warp * HID + lane * 4) = o;
}

// C = relu(g_aggh[M,K] @ W[K,128] + b), BM=128 (halves W re-staging traffic).
// fp16 MMA (m16n16k16) with W split into Wh + Wl halves -> ~fp32 W precision.
// 8 warps: wm = warp>>1 (0..3, 32 rows each), wn = warp&1 (0..1, 64 cols each).
// Epilogue runs in two 64-row halves to keep C staging under the smem limit.
// OUTH=true : *= rout, write fp16 to g_h1h  (layer 1)
// OUTH=false: pooled epilogue — accumulate relu rows into g_pool by gid
template<int K, bool OUTH>
__global__ __launch_bounds__(256) void k_gemm_h(int go,
                                                const float* __restrict__ W,
                                                const float* __restrict__ bias,
                                                const int* __restrict__ gids) {
    if (!go) return;
    constexpr int BM = 128, BN = 128, BK = 16;
    constexpr int ALD  = BK + 8;   // 24 halves (48B rows, 16B aligned)
    constexpr int WLDH = BN + 8;   // 136 halves
    constexpr int CLD  = BN + 4;   // 132 floats
    constexpr int AB_BYTES = (BM * ALD + 2 * BK * WLDH) * 2;   // 14848
    constexpr int C_BYTES  = 64 * CLD * 4;                     // 33792
    constexpr int SM_BYTES = (AB_BYTES > C_BYTES) ? AB_BYTES : C_BYTES;
    __shared__ __align__(16) char smem_raw[SM_BYTES];
    __half* Ah = (__half*)smem_raw;               // [BM][ALD]
    __half* Wh = Ah + BM * ALD;                   // [BK][WLDH]
    __half* Wl = Wh + BK * WLDH;                  // [BK][WLDH]
    float*  Cs = (float*)smem_raw;                // [64][CLD] (epilogue halves)

    int tid = threadIdx.x;
    int warp = tid >> 5;
    int wm = warp >> 1;           // 0..3
    int wn = warp & 1;            // 0..1
    int m0 = blockIdx.x * BM;

    wmma::fragment<wmma::accumulator, 16, 16, 16, float> acc[2][4];
#pragma unroll
    for (int i = 0; i < 2; i++)
#pragma unroll
        for (int j = 0; j < 4; j++) wmma::fill_fragment(acc[i][j], 0.f);

    for (int k0 = 0; k0 < K; k0 += BK) {
        // A tile: 128x16 halves = 512 uint2 slots, 2 per thread
#pragma unroll
        for (int l = 0; l < 2; l++) {
            int idx = tid * 2 + l;            // 0..511
            int row = idx >> 2, c4 = idx & 3;
            int gm = m0 + row;
            uint2 v = make_uint2(0u, 0u);
            if (gm < N_NODES) v = *(const uint2*)(g_aggh + (size_t)gm * K + k0 + c4 * 4);
            *(uint2*)&Ah[row * ALD + c4 * 4] = v;
        }
        // W tile: 16x128 fp32 -> (Wh, Wl) halves; two float4 per thread
#pragma unroll
        for (int l = 0; l < 2; l++) {
            int idx = tid + l * 256;
            int r = idx >> 5, c4 = idx & 31;
            float4 w = *(const float4*)(W + (size_t)(k0 + r) * BN + c4 * 4);
            __half2 h01 = __floats2half2_rn(w.x, w.y);
            __half2 h23 = __floats2half2_rn(w.z, w.w);
            float2 f01 = __half22float2(h01);
            float2 f23 = __half22float2(h23);
            __half2 l01 = __floats2half2_rn(w.x - f01.x, w.y - f01.y);
            __half2 l23 = __floats2half2_rn(w.z - f23.x, w.w - f23.y);
            uint2 hh, ll;
            *(__half2*)&hh.x = h01; *(__half2*)&hh.y = h23;
            *(__half2*)&ll.x = l01; *(__half2*)&ll.y = l23;
            *(uint2*)&Wh[r * WLDH + c4 * 4] = hh;
            *(uint2*)&Wl[r * WLDH + c4 * 4] = ll;
        }
        __syncthreads();

#pragma unroll
        for (int kk = 0; kk < BK; kk += 16) {
            wmma::fragment<wmma::matrix_a, 16, 16, 16, __half, wmma::row_major> a[2];
#pragma unroll
            for (int i = 0; i < 2; i++)
                wmma::load_matrix_sync(a[i], &Ah[(wm * 32 + i * 16) * ALD + kk], ALD);
#pragma unroll
            for (int j = 0; j < 4; j++) {
                wmma::fragment<wmma::matrix_b, 16, 16, 16, __half, wmma::row_major> bh, bl;
                wmma::load_matrix_sync(bh, &Wh[kk * WLDH + wn * 64 + j * 16], WLDH);
                wmma::load_matrix_sync(bl, &Wl[kk * WLDH + wn * 64 + j * 16], WLDH);
#pragma unroll
                for (int i = 0; i < 2; i++) {
                    wmma::mma_sync(acc[i][j], a[i], bh, acc[i][j]);
                    wmma::mma_sync(acc[i][j], a[i], bl, acc[i][j]);
                }
            }
        }
        __syncthreads();
    }

    // epilogue in two 64-row halves (Cs = 64 x CLD floats, unions the A/W region)
#pragma unroll
    for (int h = 0; h < 2; h++) {
        if ((wm >> 1) == h) {
#pragma unroll
            for (int i = 0; i < 2; i++)
#pragma unroll
                for (int j = 0; j < 4; j++)
                    wmma::store_matrix_sync(&Cs[((wm & 1) * 32 + i * 16) * CLD + wn * 64 + j * 16],
                                            acc[i][j], CLD, wmma::mem_row_major);
        }
        __syncthreads();
        int base = m0 + h * 64;
        if (base < N_NODES) {
            if (OUTH) {
                int row = tid >> 2, seg = tid & 3;
                int gm = base + row;
                if (gm < N_NODES) {
                    float r = g_rout[gm];
#pragma unroll
                    for (int q = 0; q < 8; q++) {
                        int col = seg * 32 + q * 4;
                        float4 v = *(float4*)&Cs[row * CLD + col];
                        uint2 u;
                        *(__half2*)&u.x = __floats2half2_rn(fmaxf(v.x + bias[col + 0], 0.f) * r,
                                                            fmaxf(v.y + bias[col + 1], 0.f) * r);
                        *(__half2*)&u.y = __floats2half2_rn(fmaxf(v.z + bias[col + 2], 0.f) * r,
                                                            fmaxf(v.w + bias[col + 3], 0.f) * r);
                        *(uint2*)(g_h1h + (size_t)gm * BN + col) = u;
                    }
                }
            } else {
                int col = tid & 127;
                int r0 = (tid >> 7) * 32;
                float bcol = bias[col];
                int nrows = min(64, N_NODES - base);
                int lim = min(r0 + 32, nrows);
                if (r0 < nrows) {
                    float acc_p = 0.f;
                    int pg = gids[base + r0];
                    for (int r = r0; r < lim; r++) {
                        int g = gids[base + r];
                        if (g != pg) {
                            atomicAdd(&g_pool[pg * HID + col], acc_p);
                            acc_p = 0.f;
                            pg = g;
                        }
                        acc_p += fmaxf(Cs[r * CLD + col] + bcol, 0.f);
                    }
                    atomicAdd(&g_pool[pg * HID + col], acc_p);
                }
            }
        }
        __syncthreads();
    }
}

// MLP head: one block per graph
__global__ void k_head(int go,
                       const float* __restrict__ Wc1, const float* __restrict__ bc1,
                       const float* __restrict__ Wc2, const float* __restrict__ bc2,
                       const float* __restrict__ Wc3, const float* __restrict__ bc3,
                       float* __restrict__ out) {
    if (!go) return;
    __shared__ float s0[HID];
    __shared__ float s1[HID];
    int g = blockIdx.x, t = threadIdx.x;
    float cnt = fmaxf((float)g_gcnt[g], 1.f);
    s0[t] = g_pool[g * HID + t] / cnt;
    __syncthreads();
    float a = bc1[t];
#pragma unroll 8
    for (int k = 0; k < HID; k++) a = fmaf(s0[k], Wc1[k * HID + t], a);
    s1[t] = fmaxf(a, 0.f);
    __syncthreads();
    float b = bc2[t];
#pragma unroll 8
    for (int k = 0; k < HID; k++) b = fmaf(s1[k], Wc2[k * HID + t], b);
    float v = fmaxf(b, 0.f);
    __syncthreads();
    s1[t] = v * Wc3[t];
    __syncthreads();
    for (int off = 64; off > 0; off >>= 1) {
        if (t < off) s1[t] += s1[t + off];
        __syncthreads();
    }
    if (t == 0) out[g] = s1[0] + bc3[0];
}

// ---------------- eager module loader ----------------
namespace {
struct EagerLoad {
    EagerLoad() {
        int ndev = 0;
        if (cudaGetDeviceCount(&ndev) != cudaSuccess || ndev <= 0) return;
        for (int d = 0; d < ndev; d++) {
            if (cudaSetDevice(d) != cudaSuccess) continue;
            void* p;
            if (cudaGetSymbolAddress(&p, g_deg_in)  == cudaSuccess) cudaMemset(p, 0, sizeof(g_deg_in));
            if (cudaGetSymbolAddress(&p, g_deg_out) == cudaSuccess) cudaMemset(p, 0, sizeof(g_deg_out));
            if (cudaGetSymbolAddress(&p, g_row_ptr) == cudaSuccess) cudaMemset(p, 0, sizeof(g_row_ptr));
            if (cudaGetSymbolAddress(&p, g_cursor)  == cudaSuccess) cudaMemset(p, 0, sizeof(g_cursor));
            if (cudaGetSymbolAddress(&p, g_csr_src) == cudaSuccess) cudaMemset(p, 0, sizeof(g_csr_src));
            if (cudaGetSymbolAddress(&p, g_rin)     == cudaSuccess) cudaMemset(p, 0, sizeof(g_rin));
            if (cudaGetSymbolAddress(&p, g_rout)    == cudaSuccess) cudaMemset(p, 0, sizeof(g_rout));
            if (cudaGetSymbolAddress(&p, g_xh)      == cudaSuccess) cudaMemset(p, 0, sizeof(g_xh));
            if (cudaGetSymbolAddress(&p, g_h1h)     == cudaSuccess) cudaMemset(p, 0, sizeof(g_h1h));
            if (cudaGetSymbolAddress(&p, g_aggh)    == cudaSuccess) cudaMemset(p, 0, sizeof(g_aggh));
            if (cudaGetSymbolAddress(&p, g_pool)    == cudaSuccess) cudaMemset(p, 0, sizeof(g_pool));
            if (cudaGetSymbolAddress(&p, g_gcnt)    == cudaSuccess) cudaMemset(p, 0, sizeof(g_gcnt));
            if (cudaGetSymbolAddress(&p, (const void*)g_ssum)  == cudaSuccess) cudaMemset(p, 0, SCAN_NB * 4);
            if (cudaGetSymbolAddress(&p, (const void*)g_sflag) == cudaSuccess) cudaMemset(p, 0, SCAN_NB * 4);

            k_zero<<<1, 32>>>(0);
            k_deg4<<<1, 32>>>(0, nullptr, nullptr);
            k_scan<<<1, SCAN_B>>>(0, nullptr);
            k_fillprep<<<1, 256>>>(0, nullptr, nullptr, nullptr);
            k_agg1h<<<1, 32>>>(0);
            k_agg2h<<<1, 32>>>(0);
            k_gemm_h<IN_DIM, true><<<1, 256>>>(0, nullptr, nullptr, nullptr);
            k_gemm_h<HID, false><<<1, 256>>>(0, nullptr, nullptr, nullptr);
            k_head<<<1, HID>>>(0, nullptr, nullptr, nullptr, nullptr, nullptr, nullptr, nullptr);
            cudaDeviceSynchronize();
        }
        cudaSetDevice(0);
        cudaGetLastError();
    }
};
static EagerLoad _eager_load_instance;
}

// ---------------- launch ----------------
// Only harness-provided pointers cross the host/device argument boundary.
extern "C" void kernel_launch(void* const* d_in, const int* in_sizes, int n_in,
                              void* d_out, int out_size) {
    const float* x    = (const float*)d_in[0];
    const int*   esrc = (const int*)d_in[1];
    const int*   edst = (const int*)d_in[2];
    const int*   gids = (const int*)d_in[3];
    const float* W1 = (const float*)d_in[4];
    const float* b1 = (const float*)d_in[5];
    const float* W2 = (const float*)d_in[6];
    const float* b2 = (const float*)d_in[7];
    const float* Wc1 = (const float*)d_in[8];
    const float* bc1 = (const float*)d_in[9];
    const float* Wc2 = (const float*)d_in[10];
    const float* bc2 = (const float*)d_in[11];
    const float* Wc3 = (const float*)d_in[12];
    const float* bc3 = (const float*)d_in[13];
    float* out = (float*)d_out;

    const int GB = (N_NODES + 127) / 128;              // 782 (BM=128)
    const int AB = (N_NODES * 32 + 255) / 256;         // 1 warp/node

    k_zero<<<(N_NODES + 255) / 256, 256>>>(1);
    k_deg4<<<(EQ4 + 255) / 256, 256>>>(1, (const int4*)esrc, (const int4*)edst);
    k_scan<<<SCAN_NB, SCAN_B>>>(1, gids);
    k_fillprep<<<FB + PB, 256>>>(1, (const int4*)esrc, (const int4*)edst, x);

    // layer 1: h1s(fp16) = relu(rin*gather(half(x*rout)) @ W1 + b1) * rout
    k_agg1h<<<AB, 256>>>(1);
    k_gemm_h<IN_DIM, true><<<GB, 256>>>(1, W1, b1, nullptr);

    // layer 2: gather + GEMM + fused mean-pool numerator (h2 never hits gmem)
    k_agg2h<<<AB, 256>>>(1);
    k_gemm_h<HID, false><<<GB, 256>>>(1, W2, b2, gids);

    // MLP head
    k_head<<<N_GRAPHS, HID>>>(1, Wc1, bc1, Wc2, bc2, Wc3, bc3, out);
}

// round 15
// speedup vs baseline: 1.0845x; 1.0675x over previous
#include <cuda_runtime.h>
#include <cuda_fp16.h>
#include <mma.h>

using namespace nvcuda;

#define N_NODES  100000
#define N_EDGES  1600000
#define N_GRAPHS 512
#define IN_DIM   64
#define HID      128

#define SCAN_B   1024
#define SCAN_NB  ((N_NODES + SCAN_B - 1) / SCAN_B)   // 98
#define EQ4      (N_EDGES / 4)                        // 400000 int4 quads
#define FB       ((EQ4 + 255) / 256)                  // 1563 fill blocks
#define PB       ((N_NODES * (IN_DIM / 2)) / 256)     // 12500 prep blocks

// ---------------- device scratch ----------------
// RULE (R3/R6): referenced ONLY inside device code; never passed as kernel
// arguments from host (host shadow address + HMM = silent corruption or
// memory-guard trips).
__device__ int    g_deg_in[N_NODES];
__device__ int    g_deg_out[N_NODES];
__device__ int    g_row_ptr[N_NODES];
__device__ int    g_cursor[N_NODES];
__device__ int    g_csr_src[N_EDGES];
__device__ float  g_rin[N_NODES];
__device__ float  g_rout[N_NODES];
__device__ __half g_xh[(size_t)N_NODES * IN_DIM];   // half(x * rout)
__device__ __half g_h1h[(size_t)N_NODES * HID];     // half(h1s)
__device__ __half g_aggh[(size_t)N_NODES * HID];    // half(agg) - GEMM A operand
__device__ float  g_pool[N_GRAPHS * HID];
__device__ int    g_gcnt[N_GRAPHS];
// single-pass scan state (re-zeroed by k_zero each call)
__device__ volatile int g_ssum[SCAN_NB];
__device__ volatile int g_sflag[SCAN_NB];

// go=0: degenerate warmup launch (forces lazy function load, touches nothing).

__global__ void k_zero(int go) {
    if (!go) return;
    int i = blockIdx.x * blockDim.x + threadIdx.x;
    if (i < N_NODES) { g_deg_in[i] = 0; g_deg_out[i] = 0; }
    if (i < N_GRAPHS * HID) g_pool[i] = 0.f;
    if (i < N_GRAPHS) g_gcnt[i] = 0;
    if (i < SCAN_NB) { g_sflag[i] = 0; g_ssum[i] = 0; }
}

// degree count, 4 edges per thread (int4 loads)
__global__ void k_deg4(int go, const int4* __restrict__ src4, const int4* __restrict__ dst4) {
    if (!go) return;
    int q = blockIdx.x * blockDim.x + threadIdx.x;
    if (q >= EQ4) return;
    int4 s = src4[q];
    int4 d = dst4[q];
    atomicAdd(&g_deg_out[s.x], 1); atomicAdd(&g_deg_out[s.y], 1);
    atomicAdd(&g_deg_out[s.z], 1); atomicAdd(&g_deg_out[s.w], 1);
    atomicAdd(&g_deg_in[d.x], 1);  atomicAdd(&g_deg_in[d.y], 1);
    atomicAdd(&g_deg_in[d.z], 1);  atomicAdd(&g_deg_in[d.w], 1);
}

// single-pass scan + CSR pointers + norms. 98 co-resident blocks -> lookback safe.
__global__ void k_scan(int go, const int* __restrict__ gids) {
    if (!go) return;
    __shared__ int s[SCAN_B];
    __shared__ int s_prefix;
    int b = blockIdx.x;
    int i = b * SCAN_B + threadIdx.x;
    int v = (i < N_NODES) ? g_deg_in[i] : 0;
    s[threadIdx.x] = v;
    __syncthreads();
    for (int off = 1; off < SCAN_B; off <<= 1) {
        int t = (threadIdx.x >= off) ? s[threadIdx.x - off] : 0;
        __syncthreads();
        s[threadIdx.x] += t;
        __syncthreads();
    }
    int incl = s[threadIdx.x];
    if (threadIdx.x == SCAN_B - 1) {
        g_ssum[b] = s[SCAN_B - 1];
        __threadfence();
        g_sflag[b] = 1;
    }
    if (threadIdx.x < 32) {
        int acc = 0;
        for (int j = threadIdx.x; j < b; j += 32) {
            while (g_sflag[j] == 0) { }
            acc += g_ssum[j];
        }
#pragma unroll
        for (int o = 16; o > 0; o >>= 1)
            acc += __shfl_down_sync(0xffffffffu, acc, o);
        if (threadIdx.x == 0) s_prefix = acc;
    }
    __syncthreads();
    if (i < N_NODES) {
        int din = v;
        int rp = incl - din + s_prefix;
        g_row_ptr[i] = rp;
        g_cursor[i]  = rp;
        g_rin[i]  = rsqrtf((float)max(din, 1));
        g_rout[i] = rsqrtf((float)max(g_deg_out[i], 1));
        atomicAdd(&g_gcnt[gids[i]], 1);
    }
}

// fused: CSR bucket fill (4 edges/thread) + g_xh = half(x * rout)
__global__ void k_fillprep(int go, const int4* __restrict__ src4,
                           const int4* __restrict__ dst4,
                           const float* __restrict__ x) {
    if (!go) return;
    int b = blockIdx.x;
    if (b < FB) {
        int q = b * blockDim.x + threadIdx.x;
        if (q >= EQ4) return;
        int4 s = src4[q];
        int4 d = dst4[q];
        g_csr_src[atomicAdd(&g_cursor[d.x], 1)] = s.x;
        g_csr_src[atomicAdd(&g_cursor[d.y], 1)] = s.y;
        g_csr_src[atomicAdd(&g_cursor[d.z], 1)] = s.z;
        g_csr_src[atomicAdd(&g_cursor[d.w], 1)] = s.w;
    } else {
        int i = (b - FB) * blockDim.x + threadIdx.x;   // half2 slot over N*64
        if (i >= N_NODES * (IN_DIM / 2)) return;
        int node = i / (IN_DIM / 2);
        float r = g_rout[node];
        float2 v = ((const float2*)x)[i];
        ((__half2*)g_xh)[i] = __floats2half2_rn(v.x * r, v.y * r);
    }
}

// layer-1 gather (R12 form): 2-way edge split, 16 dim-lanes x 4 halves
__global__ void k_agg1h(int go) {
    if (!go) return;
    int warp = (blockIdx.x * blockDim.x + threadIdx.x) >> 5;
    if (warp >= N_NODES) return;
    int lane = threadIdx.x & 31;
    int sub = lane >> 4;          // 2 edges per iteration
    int dl  = lane & 15;          // 16 lanes x 4 halves = 64
    int start = g_row_ptr[warp];
    int deg   = g_deg_in[warp];
    float a0 = 0.f, a1 = 0.f, a2 = 0.f, a3 = 0.f;
#pragma unroll 4
    for (int e = sub; e < deg; e += 2) {
        int src = g_csr_src[start + e];
        uint2 u = *(const uint2*)(g_xh + (size_t)src * IN_DIM + dl * 4);
        float2 f0 = __half22float2(*(const __half2*)&u.x);
        float2 f1 = __half22float2(*(const __half2*)&u.y);
        a0 += f0.x; a1 += f0.y; a2 += f1.x; a3 += f1.y;
    }
    a0 += __shfl_down_sync(0xffffffffu, a0, 16);
    a1 += __shfl_down_sync(0xffffffffu, a1, 16);
    a2 += __shfl_down_sync(0xffffffffu, a2, 16);
    a3 += __shfl_down_sync(0xffffffffu, a3, 16);
    if (sub == 0) {
        float r = g_rin[warp];
        uint2 o;
        *(__half2*)&o.x = __floats2half2_rn(a0 * r, a1 * r);
        *(__half2*)&o.y = __floats2half2_rn(a2 * r, a3 * r);
        *(uint2*)(g_aggh + (size_t)warp * IN_DIM + dl * 4) = o;
    }
}

// layer-2 gather (R12 form): 1 warp/node, unroll 8
__global__ void k_agg2h(int go) {
    if (!go) return;
    int warp = (blockIdx.x * blockDim.x + threadIdx.x) >> 5;
    if (warp >= N_NODES) return;
    int lane = threadIdx.x & 31;  // 32 lanes x 4 halves = 128
    int start = g_row_ptr[warp];
    int deg   = g_deg_in[warp];
    float a0 = 0.f, a1 = 0.f, a2 = 0.f, a3 = 0.f;
#pragma unroll 8
    for (int e = 0; e < deg; e++) {
        int src = g_csr_src[start + e];
        uint2 u = *(const uint2*)(g_h1h + (size_t)src * HID + lane * 4);
        float2 f0 = __half22float2(*(const __half2*)&u.x);
        float2 f1 = __half22float2(*(const __half2*)&u.y);
        a0 += f0.x; a1 += f0.y; a2 += f1.x; a3 += f1.y;
    }
    float r = g_rin[warp];
    uint2 o;
    *(__half2*)&o.x = __floats2half2_rn(a0 * r, a1 * r);
    *(__half2*)&o.y = __floats2half2_rn(a2 * r, a3 * r);
    *(uint2*)(g_aggh + (size_t)warp * HID + lane * 4) = o;
}

// C = relu(g_aggh[M,K] @ W[K,128] + b), BM=64 (R12 structure).
// BK = K for K=64 (whole-K resident: one staging + one sync pair, 44KB smem);
// BK = 16 for K=128 (R12 path unchanged).
// fp16 MMA (m16n16k16) with W split into Wh + Wl halves -> ~fp32 W precision.
// OUTH=true : *= rout, write fp16 to g_h1h  (layer 1)
// OUTH=false: pooled epilogue — accumulate relu rows into g_pool by gid
template<int K, bool OUTH>
__global__ __launch_bounds__(256) void k_gemm_h(int go,
                                                const float* __restrict__ W,
                                                const float* __restrict__ bias,
                                                const int* __restrict__ gids) {
    if (!go) return;
    constexpr int BM = 64, BN = 128;
    constexpr int BK = (K == 64) ? 64 : 16;
    constexpr int ALD  = BK + 8;   // halves; row bytes = 2*(BK+8), 16B-aligned
    constexpr int WLDH = BN + 8;   // halves
    constexpr int CLD  = BN + 4;   // floats
    constexpr int AB_BYTES = (BM * ALD + 2 * BK * WLDH) * 2;   // K=64: 44032, K=128: 11776
    constexpr int C_BYTES  = BM * CLD * 4;                     // 33792
    constexpr int SM_BYTES = (AB_BYTES > C_BYTES) ? AB_BYTES : C_BYTES;
    __shared__ __align__(16) char smem_raw[SM_BYTES];
    __half* Ah = (__half*)smem_raw;               // [BM][ALD]
    __half* Wh = Ah + BM * ALD;                   // [BK][WLDH]
    __half* Wl = Wh + BK * WLDH;                  // [BK][WLDH]
    float*  Cs = (float*)smem_raw;                // [BM][CLD] (epilogue)

    int tid = threadIdx.x;
    int warp = tid >> 5;
    int wm = warp >> 2;           // 0..1 (32 rows each)
    int wn = warp & 3;            // 0..3 (32 cols each)
    int m0 = blockIdx.x * BM;

    wmma::fragment<wmma::accumulator, 16, 16, 16, float> acc[2][2];
#pragma unroll
    for (int i = 0; i < 2; i++)
#pragma unroll
        for (int j = 0; j < 2; j++) wmma::fill_fragment(acc[i][j], 0.f);

    for (int k0 = 0; k0 < K; k0 += BK) {
        // A tile: BM x BK halves, uint2 (4 halves) granularity
#pragma unroll
        for (int idx = tid; idx < BM * (BK / 4); idx += 256) {
            int row = idx / (BK / 4), c4 = idx % (BK / 4);
            int gm = m0 + row;
            uint2 v = make_uint2(0u, 0u);
            if (gm < N_NODES) v = *(const uint2*)(g_aggh + (size_t)gm * K + k0 + c4 * 4);
            *(uint2*)&Ah[row * ALD + c4 * 4] = v;
        }
        // W tile: BK x 128 fp32 -> (Wh, Wl) halves; float4 granularity
#pragma unroll
        for (int idx = tid; idx < BK * 32; idx += 256) {
            int r = idx >> 5, c4 = idx & 31;
            float4 w = *(const float4*)(W + (size_t)(k0 + r) * BN + c4 * 4);
            __half2 h01 = __floats2half2_rn(w.x, w.y);
            __half2 h23 = __floats2half2_rn(w.z, w.w);
            float2 f01 = __half22float2(h01);
            float2 f23 = __half22float2(h23);
            __half2 l01 = __floats2half2_rn(w.x - f01.x, w.y - f01.y);
            __half2 l23 = __floats2half2_rn(w.z - f23.x, w.w - f23.y);
            uint2 hh, ll;
            *(__half2*)&hh.x = h01; *(__half2*)&hh.y = h23;
            *(__half2*)&ll.x = l01; *(__half2*)&ll.y = l23;
            *(uint2*)&Wh[r * WLDH + c4 * 4] = hh;
            *(uint2*)&Wl[r * WLDH + c4 * 4] = ll;
        }
        __syncthreads();

#pragma unroll
        for (int kk = 0; kk < BK; kk += 16) {
            wmma::fragment<wmma::matrix_a, 16, 16, 16, __half, wmma::row_major> a[2];
            wmma::fragment<wmma::matrix_b, 16, 16, 16, __half, wmma::row_major> bh[2], bl[2];
#pragma unroll
            for (int i = 0; i < 2; i++)
                wmma::load_matrix_sync(a[i], &Ah[(wm * 32 + i * 16) * ALD + kk], ALD);
#pragma unroll
            for (int j = 0; j < 2; j++) {
                wmma::load_matrix_sync(bh[j], &Wh[kk * WLDH + wn * 32 + j * 16], WLDH);
                wmma::load_matrix_sync(bl[j], &Wl[kk * WLDH + wn * 32 + j * 16], WLDH);
            }
#pragma unroll
            for (int i = 0; i < 2; i++)
#pragma unroll
                for (int j = 0; j < 2; j++) {
                    wmma::mma_sync(acc[i][j], a[i], bh[j], acc[i][j]);
                    wmma::mma_sync(acc[i][j], a[i], bl[j], acc[i][j]);
                }
        }
        __syncthreads();
    }

#pragma unroll
    for (int i = 0; i < 2; i++)
#pragma unroll
        for (int j = 0; j < 2; j++)
            wmma::store_matrix_sync(&Cs[(wm * 32 + i * 16) * CLD + wn * 32 + j * 16],
                                    acc[i][j], CLD, wmma::mem_row_major);
    __syncthreads();

    if (OUTH) {
        // layer-1 epilogue: bias + relu, * rout, fp16 out
        int row = tid >> 2, seg = tid & 3;
        int gm = m0 + row;
        if (gm < N_NODES) {
            float r = g_rout[gm];
#pragma unroll
            for (int q = 0; q < 8; q++) {
                int col = seg * 32 + q * 4;
                float4 v = *(float4*)&Cs[row * CLD + col];
                uint2 u;
                *(__half2*)&u.x = __floats2half2_rn(fmaxf(v.x + bias[col + 0], 0.f) * r,
                                                    fmaxf(v.y + bias[col + 1], 0.f) * r);
                *(__half2*)&u.y = __floats2half2_rn(fmaxf(v.z + bias[col + 2], 0.f) * r,
                                                    fmaxf(v.w + bias[col + 3], 0.f) * r);
                *(uint2*)(g_h1h + (size_t)gm * BN + col) = u;
            }
        }
    } else {
        // layer-2 pooled epilogue: run-length accumulate by sorted gid
        int col = tid & 127;
        int r0 = (tid >> 7) * 32;
        float bcol = bias[col];
        int nrows = min(BM, N_NODES - m0);
        int lim = min(r0 + 32, nrows);
        if (r0 < nrows) {
            float acc_p = 0.f;
            int pg = gids[m0 + r0];
            for (int r = r0; r < lim; r++) {
                int g = gids[m0 + r];
                if (g != pg) {
                    atomicAdd(&g_pool[pg * HID + col], acc_p);
                    acc_p = 0.f;
                    pg = g;
                }
                acc_p += fmaxf(Cs[r * CLD + col] + bcol, 0.f);
            }
            atomicAdd(&g_pool[pg * HID + col], acc_p);
        }
    }
}

// MLP head: one block per graph
__global__ void k_head(int go,
                       const float* __restrict__ Wc1, const float* __restrict__ bc1,
                       const float* __restrict__ Wc2, const float* __restrict__ bc2,
                       const float* __restrict__ Wc3, const float* __restrict__ bc3,
                       float* __restrict__ out) {
    if (!go) return;
    __shared__ float s0[HID];
    __shared__ float s1[HID];
    int g = blockIdx.x, t = threadIdx.x;
    float cnt = fmaxf((float)g_gcnt[g], 1.f);
    s0[t] = g_pool[g * HID + t] / cnt;
    __syncthreads();
    float a = bc1[t];
#pragma unroll 8
    for (int k = 0; k < HID; k++) a = fmaf(s0[k], Wc1[k * HID + t], a);
    s1[t] = fmaxf(a, 0.f);
    __syncthreads();
    float b = bc2[t];
#pragma unroll 8
    for (int k = 0; k < HID; k++) b = fmaf(s1[k], Wc2[k * HID + t], b);
    float v = fmaxf(b, 0.f);
    __syncthreads();
    s1[t] = v * Wc3[t];
    __syncthreads();
    for (int off = 64; off > 0; off >>= 1) {
        if (t < off) s1[t] += s1[t + off];
        __syncthreads();
    }
    if (t == 0) out[g] = s1[0] + bc3[0];
}

// ---------------- eager module loader ----------------
namespace {
struct EagerLoad {
    EagerLoad() {
        int ndev = 0;
        if (cudaGetDeviceCount(&ndev) != cudaSuccess || ndev <= 0) return;
        for (int d = 0; d < ndev; d++) {
            if (cudaSetDevice(d) != cudaSuccess) continue;
            void* p;
            if (cudaGetSymbolAddress(&p, g_deg_in)  == cudaSuccess) cudaMemset(p, 0, sizeof(g_deg_in));
            if (cudaGetSymbolAddress(&p, g_deg_out) == cudaSuccess) cudaMemset(p, 0, sizeof(g_deg_out));
            if (cudaGetSymbolAddress(&p, g_row_ptr) == cudaSuccess) cudaMemset(p, 0, sizeof(g_row_ptr));
            if (cudaGetSymbolAddress(&p, g_cursor)  == cudaSuccess) cudaMemset(p, 0, sizeof(g_cursor));
            if (cudaGetSymbolAddress(&p, g_csr_src) == cudaSuccess) cudaMemset(p, 0, sizeof(g_csr_src));
            if (cudaGetSymbolAddress(&p, g_rin)     == cudaSuccess) cudaMemset(p, 0, sizeof(g_rin));
            if (cudaGetSymbolAddress(&p, g_rout)    == cudaSuccess) cudaMemset(p, 0, sizeof(g_rout));
            if (cudaGetSymbolAddress(&p, g_xh)      == cudaSuccess) cudaMemset(p, 0, sizeof(g_xh));
            if (cudaGetSymbolAddress(&p, g_h1h)     == cudaSuccess) cudaMemset(p, 0, sizeof(g_h1h));
            if (cudaGetSymbolAddress(&p, g_aggh)    == cudaSuccess) cudaMemset(p, 0, sizeof(g_aggh));
            if (cudaGetSymbolAddress(&p, g_pool)    == cudaSuccess) cudaMemset(p, 0, sizeof(g_pool));
            if (cudaGetSymbolAddress(&p, g_gcnt)    == cudaSuccess) cudaMemset(p, 0, sizeof(g_gcnt));
            if (cudaGetSymbolAddress(&p, (const void*)g_ssum)  == cudaSuccess) cudaMemset(p, 0, SCAN_NB * 4);
            if (cudaGetSymbolAddress(&p, (const void*)g_sflag) == cudaSuccess) cudaMemset(p, 0, SCAN_NB * 4);

            k_zero<<<1, 32>>>(0);
            k_deg4<<<1, 32>>>(0, nullptr, nullptr);
            k_scan<<<1, SCAN_B>>>(0, nullptr);
            k_fillprep<<<1, 256>>>(0, nullptr, nullptr, nullptr);
            k_agg1h<<<1, 32>>>(0);
            k_agg2h<<<1, 32>>>(0);
            k_gemm_h<IN_DIM, true><<<1, 256>>>(0, nullptr, nullptr, nullptr);
            k_gemm_h<HID, false><<<1, 256>>>(0, nullptr, nullptr, nullptr);
            k_head<<<1, HID>>>(0, nullptr, nullptr, nullptr, nullptr, nullptr, nullptr, nullptr);
            cudaDeviceSynchronize();
        }
        cudaSetDevice(0);
        cudaGetLastError();
    }
};
static EagerLoad _eager_load_instance;
}

// ---------------- launch ----------------
// Only harness-provided pointers cross the host/device argument boundary.
extern "C" void kernel_launch(void* const* d_in, const int* in_sizes, int n_in,
                              void* d_out, int out_size) {
    const float* x    = (const float*)d_in[0];
    const int*   esrc = (const int*)d_in[1];
    const int*   edst = (const int*)d_in[2];
    const int*   gids = (const int*)d_in[3];
    const float* W1 = (const float*)d_in[4];
    const float* b1 = (const float*)d_in[5];
    const float* W2 = (const float*)d_in[6];
    const float* b2 = (const float*)d_in[7];
    const float* Wc1 = (const float*)d_in[8];
    const float* bc1 = (const float*)d_in[9];
    const float* Wc2 = (const float*)d_in[10];
    const float* bc2 = (const float*)d_in[11];
    const float* Wc3 = (const float*)d_in[12];
    const float* bc3 = (const float*)d_in[13];
    float* out = (float*)d_out;

    const int GB = (N_NODES + 63) / 64;                // 1563 (BM=64)
    const int AB = (N_NODES * 32 + 255) / 256;         // 1 warp/node

    k_zero<<<(N_NODES + 255) / 256, 256>>>(1);
    k_deg4<<<(EQ4 + 255) / 256, 256>>>(1, (const int4*)esrc, (const int4*)edst);
    k_scan<<<SCAN_NB, SCAN_B>>>(1, gids);
    k_fillprep<<<FB + PB, 256>>>(1, (const int4*)esrc, (const int4*)edst, x);

    // layer 1: h1s(fp16) = relu(rin*gather(half(x*rout)) @ W1 + b1) * rout
    k_agg1h<<<AB, 256>>>(1);
    k_gemm_h<IN_DIM, true><<<GB, 256>>>(1, W1, b1, nullptr);

    // layer 2: gather + GEMM + fused mean-pool numerator (h2 never hits gmem)
    k_agg2h<<<AB, 256>>>(1);
    k_gemm_h<HID, false><<<GB, 256>>>(1, W2, b2, gids);

    // MLP head
    k_head<<<N_GRAPHS, HID>>>(1, Wc1, bc1, Wc2, bc2, Wc3, bc3, out);
}

// round 16
// speedup vs baseline: 1.0911x; 1.0061x over previous
#include <cuda_runtime.h>
#include <cuda_fp16.h>
#include <mma.h>

using namespace nvcuda;

#define N_NODES  100000
#define N_EDGES  1600000
#define N_GRAPHS 512
#define IN_DIM   64
#define HID      128

#define SCAN_B   1024
#define SCAN_NB  ((N_NODES + SCAN_B - 1) / SCAN_B)   // 98
#define EQ4      (N_EDGES / 4)                        // 400000 int4 quads
#define FB       ((EQ4 + 255) / 256)                  // 1563 fill blocks
#define PB       ((N_NODES * (IN_DIM / 2)) / 256)     // 12500 prep blocks

// GEMM smem sizing (whole-K resident): BM=64, BN=128, BK=K
constexpr int gemm_smem_bytes(int K) {
    int ALD = K + 8, WLDH = 128 + 8, CLD = 128 + 4;
    int ab = (64 * ALD + 2 * K * WLDH) * 2;
    int c  = 64 * CLD * 4;
    return ab > c ? ab : c;
}

// ---------------- device scratch ----------------
// RULE (R3/R6): referenced ONLY inside device code; never passed as kernel
// arguments from host (host shadow address + HMM = silent corruption or
// memory-guard trips).
__device__ int    g_deg_in[N_NODES];
__device__ int    g_deg_out[N_NODES];
__device__ int    g_row_ptr[N_NODES];
__device__ int    g_cursor[N_NODES];
__device__ int    g_csr_src[N_EDGES];
__device__ float  g_rin[N_NODES];
__device__ float  g_rout[N_NODES];
__device__ __half g_xh[(size_t)N_NODES * IN_DIM];   // half(x * rout)
__device__ __half g_h1h[(size_t)N_NODES * HID];     // half(h1s)
__device__ __half g_aggh[(size_t)N_NODES * HID];    // half(agg) - GEMM A operand
__device__ float  g_pool[N_GRAPHS * HID];
__device__ int    g_gcnt[N_GRAPHS];
// single-pass scan state (re-zeroed by k_zero each call)
__device__ volatile int g_ssum[SCAN_NB];
__device__ volatile int g_sflag[SCAN_NB];

// go=0: degenerate warmup launch (forces lazy function load, touches nothing).

__global__ void k_zero(int go) {
    if (!go) return;
    int i = blockIdx.x * blockDim.x + threadIdx.x;
    if (i < N_NODES) { g_deg_in[i] = 0; g_deg_out[i] = 0; }
    if (i < N_GRAPHS * HID) g_pool[i] = 0.f;
    if (i < N_GRAPHS) g_gcnt[i] = 0;
    if (i < SCAN_NB) { g_sflag[i] = 0; g_ssum[i] = 0; }
}

// degree count, 4 edges per thread (int4 loads)
__global__ void k_deg4(int go, const int4* __restrict__ src4, const int4* __restrict__ dst4) {
    if (!go) return;
    int q = blockIdx.x * blockDim.x + threadIdx.x;
    if (q >= EQ4) return;
    int4 s = src4[q];
    int4 d = dst4[q];
    atomicAdd(&g_deg_out[s.x], 1); atomicAdd(&g_deg_out[s.y], 1);
    atomicAdd(&g_deg_out[s.z], 1); atomicAdd(&g_deg_out[s.w], 1);
    atomicAdd(&g_deg_in[d.x], 1);  atomicAdd(&g_deg_in[d.y], 1);
    atomicAdd(&g_deg_in[d.z], 1);  atomicAdd(&g_deg_in[d.w], 1);
}

// single-pass scan + CSR pointers + norms. 98 co-resident blocks -> lookback safe.
__global__ void k_scan(int go, const int* __restrict__ gids) {
    if (!go) return;
    __shared__ int s[SCAN_B];
    __shared__ int s_prefix;
    int b = blockIdx.x;
    int i = b * SCAN_B + threadIdx.x;
    int v = (i < N_NODES) ? g_deg_in[i] : 0;
    s[threadIdx.x] = v;
    __syncthreads();
    for (int off = 1; off < SCAN_B; off <<= 1) {
        int t = (threadIdx.x >= off) ? s[threadIdx.x - off] : 0;
        __syncthreads();
        s[threadIdx.x] += t;
        __syncthreads();
    }
    int incl = s[threadIdx.x];
    if (threadIdx.x == SCAN_B - 1) {
        g_ssum[b] = s[SCAN_B - 1];
        __threadfence();
        g_sflag[b] = 1;
    }
    if (threadIdx.x < 32) {
        int acc = 0;
        for (int j = threadIdx.x; j < b; j += 32) {
            while (g_sflag[j] == 0) { }
            acc += g_ssum[j];
        }
#pragma unroll
        for (int o = 16; o > 0; o >>= 1)
            acc += __shfl_down_sync(0xffffffffu, acc, o);
        if (threadIdx.x == 0) s_prefix = acc;
    }
    __syncthreads();
    if (i < N_NODES) {
        int din = v;
        int rp = incl - din + s_prefix;
        g_row_ptr[i] = rp;
        g_cursor[i]  = rp;
        g_rin[i]  = rsqrtf((float)max(din, 1));
        g_rout[i] = rsqrtf((float)max(g_deg_out[i], 1));
        atomicAdd(&g_gcnt[gids[i]], 1);
    }
}

// fused: CSR bucket fill (4 edges/thread) + g_xh = half(x * rout)
__global__ void k_fillprep(int go, const int4* __restrict__ src4,
                           const int4* __restrict__ dst4,
                           const float* __restrict__ x) {
    if (!go) return;
    int b = blockIdx.x;
    if (b < FB) {
        int q = b * blockDim.x + threadIdx.x;
        if (q >= EQ4) return;
        int4 s = src4[q];
        int4 d = dst4[q];
        g_csr_src[atomicAdd(&g_cursor[d.x], 1)] = s.x;
        g_csr_src[atomicAdd(&g_cursor[d.y], 1)] = s.y;
        g_csr_src[atomicAdd(&g_cursor[d.z], 1)] = s.z;
        g_csr_src[atomicAdd(&g_cursor[d.w], 1)] = s.w;
    } else {
        int i = (b - FB) * blockDim.x + threadIdx.x;   // half2 slot over N*64
        if (i >= N_NODES * (IN_DIM / 2)) return;
        int node = i / (IN_DIM / 2);
        float r = g_rout[node];
        float2 v = ((const float2*)x)[i];
        ((__half2*)g_xh)[i] = __floats2half2_rn(v.x * r, v.y * r);
    }
}

// layer-1 gather (R12 form): 2-way edge split, 16 dim-lanes x 4 halves
__global__ void k_agg1h(int go) {
    if (!go) return;
    int warp = (blockIdx.x * blockDim.x + threadIdx.x) >> 5;
    if (warp >= N_NODES) return;
    int lane = threadIdx.x & 31;
    int sub = lane >> 4;          // 2 edges per iteration
    int dl  = lane & 15;          // 16 lanes x 4 halves = 64
    int start = g_row_ptr[warp];
    int deg   = g_deg_in[warp];
    float a0 = 0.f, a1 = 0.f, a2 = 0.f, a3 = 0.f;
#pragma unroll 4
    for (int e = sub; e < deg; e += 2) {
        int src = g_csr_src[start + e];
        uint2 u = *(const uint2*)(g_xh + (size_t)src * IN_DIM + dl * 4);
        float2 f0 = __half22float2(*(const __half2*)&u.x);
        float2 f1 = __half22float2(*(const __half2*)&u.y);
        a0 += f0.x; a1 += f0.y; a2 += f1.x; a3 += f1.y;
    }
    a0 += __shfl_down_sync(0xffffffffu, a0, 16);
    a1 += __shfl_down_sync(0xffffffffu, a1, 16);
    a2 += __shfl_down_sync(0xffffffffu, a2, 16);
    a3 += __shfl_down_sync(0xffffffffu, a3, 16);
    if (sub == 0) {
        float r = g_rin[warp];
        uint2 o;
        *(__half2*)&o.x = __floats2half2_rn(a0 * r, a1 * r);
        *(__half2*)&o.y = __floats2half2_rn(a2 * r, a3 * r);
        *(uint2*)(g_aggh + (size_t)warp * IN_DIM + dl * 4) = o;
    }
}

// layer-2 gather (R12 form): 1 warp/node, unroll 8
__global__ void k_agg2h(int go) {
    if (!go) return;
    int warp = (blockIdx.x * blockDim.x + threadIdx.x) >> 5;
    if (warp >= N_NODES) return;
    int lane = threadIdx.x & 31;  // 32 lanes x 4 halves = 128
    int start = g_row_ptr[warp];
    int deg   = g_deg_in[warp];
    float a0 = 0.f, a1 = 0.f, a2 = 0.f, a3 = 0.f;
#pragma unroll 8
    for (int e = 0; e < deg; e++) {
        int src = g_csr_src[start + e];
        uint2 u = *(const uint2*)(g_h1h + (size_t)src * HID + lane * 4);
        float2 f0 = __half22float2(*(const __half2*)&u.x);
        float2 f1 = __half22float2(*(const __half2*)&u.y);
        a0 += f0.x; a1 += f0.y; a2 += f1.x; a3 += f1.y;
    }
    float r = g_rin[warp];
    uint2 o;
    *(__half2*)&o.x = __floats2half2_rn(a0 * r, a1 * r);
    *(__half2*)&o.y = __floats2half2_rn(a2 * r, a3 * r);
    *(uint2*)(g_aggh + (size_t)warp * HID + lane * 4) = o;
}

// C = relu(g_aggh[M,K] @ W[K,128] + b), BM=64, whole-K resident (BK = K):
// single staging + single sync pair, then all MMAs run from resident smem.
// K=64: 44 KB smem; K=128: 87 KB (dynamic, opt-in set in EagerLoad).
// fp16 MMA (m16n16k16) with W split into Wh + Wl halves -> ~fp32 W precision.
// OUTH=true : *= rout, write fp16 to g_h1h  (layer 1)
// OUTH=false: pooled epilogue — accumulate relu rows into g_pool by gid
template<int K, bool OUTH>
__global__ __launch_bounds__(256) void k_gemm_h(int go,
                                                const float* __restrict__ W,
                                                const float* __restrict__ bias,
                                                const int* __restrict__ gids) {
    if (!go) return;
    constexpr int BM = 64, BN = 128, BK = K;
    constexpr int ALD  = BK + 8;   // halves
    constexpr int WLDH = BN + 8;   // halves
    constexpr int CLD  = BN + 4;   // floats
    extern __shared__ __align__(16) char smem_raw[];
    __half* Ah = (__half*)smem_raw;               // [BM][ALD]
    __half* Wh = Ah + BM * ALD;                   // [BK][WLDH]
    __half* Wl = Wh + BK * WLDH;                  // [BK][WLDH]
    float*  Cs = (float*)smem_raw;                // [BM][CLD] (epilogue)

    int tid = threadIdx.x;
    int warp = tid >> 5;
    int wm = warp >> 2;           // 0..1 (32 rows each)
    int wn = warp & 3;            // 0..3 (32 cols each)
    int m0 = blockIdx.x * BM;

    wmma::fragment<wmma::accumulator, 16, 16, 16, float> acc[2][2];
#pragma unroll
    for (int i = 0; i < 2; i++)
#pragma unroll
        for (int j = 0; j < 2; j++) wmma::fill_fragment(acc[i][j], 0.f);

    // A tile: BM x K halves, uint2 (4 halves) granularity — staged once
#pragma unroll
    for (int idx = tid; idx < BM * (BK / 4); idx += 256) {
        int row = idx / (BK / 4), c4 = idx % (BK / 4);
        int gm = m0 + row;
        uint2 v = make_uint2(0u, 0u);
        if (gm < N_NODES) v = *(const uint2*)(g_aggh + (size_t)gm * K + c4 * 4);
        *(uint2*)&Ah[row * ALD + c4 * 4] = v;
    }
    // W tile: K x 128 fp32 -> (Wh, Wl) halves; float4 granularity — staged once
#pragma unroll
    for (int idx = tid; idx < BK * 32; idx += 256) {
        int r = idx >> 5, c4 = idx & 31;
        float4 w = *(const float4*)(W + (size_t)r * BN + c4 * 4);
        __half2 h01 = __floats2half2_rn(w.x, w.y);
        __half2 h23 = __floats2half2_rn(w.z, w.w);
        float2 f01 = __half22float2(h01);
        float2 f23 = __half22float2(h23);
        __half2 l01 = __floats2half2_rn(w.x - f01.x, w.y - f01.y);
        __half2 l23 = __floats2half2_rn(w.z - f23.x, w.w - f23.y);
        uint2 hh, ll;
        *(__half2*)&hh.x = h01; *(__half2*)&hh.y = h23;
        *(__half2*)&ll.x = l01; *(__half2*)&ll.y = l23;
        *(uint2*)&Wh[r * WLDH + c4 * 4] = hh;
        *(uint2*)&Wl[r * WLDH + c4 * 4] = ll;
    }
    __syncthreads();

#pragma unroll
    for (int kk = 0; kk < BK; kk += 16) {
        wmma::fragment<wmma::matrix_a, 16, 16, 16, __half, wmma::row_major> a[2];
        wmma::fragment<wmma::matrix_b, 16, 16, 16, __half, wmma::row_major> bh[2], bl[2];
#pragma unroll
        for (int i = 0; i < 2; i++)
            wmma::load_matrix_sync(a[i], &Ah[(wm * 32 + i * 16) * ALD + kk], ALD);
#pragma unroll
        for (int j = 0; j < 2; j++) {
            wmma::load_matrix_sync(bh[j], &Wh[kk * WLDH + wn * 32 + j * 16], WLDH);
            wmma::load_matrix_sync(bl[j], &Wl[kk * WLDH + wn * 32 + j * 16], WLDH);
        }
#pragma unroll
        for (int i = 0; i < 2; i++)
#pragma unroll
            for (int j = 0; j < 2; j++) {
                wmma::mma_sync(acc[i][j], a[i], bh[j], acc[i][j]);
                wmma::mma_sync(acc[i][j], a[i], bl[j], acc[i][j]);
            }
    }
    __syncthreads();

#pragma unroll
    for (int i = 0; i < 2; i++)
#pragma unroll
        for (int j = 0; j < 2; j++)
            wmma::store_matrix_sync(&Cs[(wm * 32 + i * 16) * CLD + wn * 32 + j * 16],
                                    acc[i][j], CLD, wmma::mem_row_major);
    __syncthreads();

    if (OUTH) {
        // layer-1 epilogue: bias + relu, * rout, fp16 out
        int row = tid >> 2, seg = tid & 3;
        int gm = m0 + row;
        if (gm < N_NODES) {
            float r = g_rout[gm];
#pragma unroll
            for (int q = 0; q < 8; q++) {
                int col = seg * 32 + q * 4;
                float4 v = *(float4*)&Cs[row * CLD + col];
                uint2 u;
                *(__half2*)&u.x = __floats2half2_rn(fmaxf(v.x + bias[col + 0], 0.f) * r,
                                                    fmaxf(v.y + bias[col + 1], 0.f) * r);
                *(__half2*)&u.y = __floats2half2_rn(fmaxf(v.z + bias[col + 2], 0.f) * r,
                                                    fmaxf(v.w + bias[col + 3], 0.f) * r);
                *(uint2*)(g_h1h + (size_t)gm * BN + col) = u;
            }
        }
    } else {
        // layer-2 pooled epilogue: run-length accumulate by sorted gid
        int col = tid & 127;
        int r0 = (tid >> 7) * 32;
        float bcol = bias[col];
        int nrows = min(BM, N_NODES - m0);
        int lim = min(r0 + 32, nrows);
        if (r0 < nrows) {
            float acc_p = 0.f;
            int pg = gids[m0 + r0];
            for (int r = r0; r < lim; r++) {
                int g = gids[m0 + r];
                if (g != pg) {
                    atomicAdd(&g_pool[pg * HID + col], acc_p);
                    acc_p = 0.f;
                    pg = g;
                }
                acc_p += fmaxf(Cs[r * CLD + col] + bcol, 0.f);
            }
            atomicAdd(&g_pool[pg * HID + col], acc_p);
        }
    }
}

// MLP head: one block per graph
__global__ void k_head(int go,
                       const float* __restrict__ Wc1, const float* __restrict__ bc1,
                       const float* __restrict__ Wc2, const float* __restrict__ bc2,
                       const float* __restrict__ Wc3, const float* __restrict__ bc3,
                       float* __restrict__ out) {
    if (!go) return;
    __shared__ float s0[HID];
    __shared__ float s1[HID];
    int g = blockIdx.x, t = threadIdx.x;
    float cnt = fmaxf((float)g_gcnt[g], 1.f);
    s0[t] = g_pool[g * HID + t] / cnt;
    __syncthreads();
    float a = bc1[t];
#pragma unroll 8
    for (int k = 0; k < HID; k++) a = fmaf(s0[k], Wc1[k * HID + t], a);
    s1[t] = fmaxf(a, 0.f);
    __syncthreads();
    float b = bc2[t];
#pragma unroll 8
    for (int k = 0; k < HID; k++) b = fmaf(s1[k], Wc2[k * HID + t], b);
    float v = fmaxf(b, 0.f);
    __syncthreads();
    s1[t] = v * Wc3[t];
    __syncthreads();
    for (int off = 64; off > 0; off >>= 1) {
        if (t < off) s1[t] += s1[t + off];
        __syncthreads();
    }
    if (t == 0) out[g] = s1[0] + bc3[0];
}

// ---------------- eager module loader ----------------
namespace {
struct EagerLoad {
    EagerLoad() {
        int ndev = 0;
        if (cudaGetDeviceCount(&ndev) != cudaSuccess || ndev <= 0) return;
        for (int d = 0; d < ndev; d++) {
            if (cudaSetDevice(d) != cudaSuccess) continue;
            void* p;
            if (cudaGetSymbolAddress(&p, g_deg_in)  == cudaSuccess) cudaMemset(p, 0, sizeof(g_deg_in));
            if (cudaGetSymbolAddress(&p, g_deg_out) == cudaSuccess) cudaMemset(p, 0, sizeof(g_deg_out));
            if (cudaGetSymbolAddress(&p, g_row_ptr) == cudaSuccess) cudaMemset(p, 0, sizeof(g_row_ptr));
            if (cudaGetSymbolAddress(&p, g_cursor)  == cudaSuccess) cudaMemset(p, 0, sizeof(g_cursor));
            if (cudaGetSymbolAddress(&p, g_csr_src) == cudaSuccess) cudaMemset(p, 0, sizeof(g_csr_src));
            if (cudaGetSymbolAddress(&p, g_rin)     == cudaSuccess) cudaMemset(p, 0, sizeof(g_rin));
            if (cudaGetSymbolAddress(&p, g_rout)    == cudaSuccess) cudaMemset(p, 0, sizeof(g_rout));
            if (cudaGetSymbolAddress(&p, g_xh)      == cudaSuccess) cudaMemset(p, 0, sizeof(g_xh));
            if (cudaGetSymbolAddress(&p, g_h1h)     == cudaSuccess) cudaMemset(p, 0, sizeof(g_h1h));
            if (cudaGetSymbolAddress(&p, g_aggh)    == cudaSuccess) cudaMemset(p, 0, sizeof(g_aggh));
            if (cudaGetSymbolAddress(&p, g_pool)    == cudaSuccess) cudaMemset(p, 0, sizeof(g_pool));
            if (cudaGetSymbolAddress(&p, g_gcnt)    == cudaSuccess) cudaMemset(p, 0, sizeof(g_gcnt));
            if (cudaGetSymbolAddress(&p, (const void*)g_ssum)  == cudaSuccess) cudaMemset(p, 0, SCAN_NB * 4);
            if (cudaGetSymbolAddress(&p, (const void*)g_sflag) == cudaSuccess) cudaMemset(p, 0, SCAN_NB * 4);

            // opt-in to large dynamic smem for the whole-K GEMMs (attribute, not allocation)
            cudaFuncSetAttribute(k_gemm_h<IN_DIM, true>,
                                 cudaFuncAttributeMaxDynamicSharedMemorySize,
                                 gemm_smem_bytes(IN_DIM));
            cudaFuncSetAttribute(k_gemm_h<HID, false>,
                                 cudaFuncAttributeMaxDynamicSharedMemorySize,
                                 gemm_smem_bytes(HID));

            k_zero<<<1, 32>>>(0);
            k_deg4<<<1, 32>>>(0, nullptr, nullptr);
            k_scan<<<1, SCAN_B>>>(0, nullptr);
            k_fillprep<<<1, 256>>>(0, nullptr, nullptr, nullptr);
            k_agg1h<<<1, 32>>>(0);
            k_agg2h<<<1, 32>>>(0);
            k_gemm_h<IN_DIM, true><<<1, 256, gemm_smem_bytes(IN_DIM)>>>(0, nullptr, nullptr, nullptr);
            k_gemm_h<HID, false><<<1, 256, gemm_smem_bytes(HID)>>>(0, nullptr, nullptr, nullptr);
            k_head<<<1, HID>>>(0, nullptr, nullptr, nullptr, nullptr, nullptr, nullptr, nullptr);
            cudaDeviceSynchronize();
        }
        cudaSetDevice(0);
        cudaGetLastError();
    }
};
static EagerLoad _eager_load_instance;
}

// ---------------- launch ----------------
// Only harness-provided pointers cross the host/device argument boundary.
extern "C" void kernel_launch(void* const* d_in, const int* in_sizes, int n_in,
                              void* d_out, int out_size) {
    const float* x    = (const float*)d_in[0];
    const int*   esrc = (const int*)d_in[1];
    const int*   edst = (const int*)d_in[2];
    const int*   gids = (const int*)d_in[3];
    const float* W1 = (const float*)d_in[4];
    const float* b1 = (const float*)d_in[5];
    const float* W2 = (const float*)d_in[6];
    const float* b2 = (const float*)d_in[7];
    const float* Wc1 = (const float*)d_in[8];
    const float* bc1 = (const float*)d_in[9];
    const float* Wc2 = (const float*)d_in[10];
    const float* bc2 = (const float*)d_in[11];
    const float* Wc3 = (const float*)d_in[12];
    const float* bc3 = (const float*)d_in[13];
    float* out = (float*)d_out;

    const int GB = (N_NODES + 63) / 64;                // 1563 (BM=64)
    const int AB = (N_NODES * 32 + 255) / 256;         // 1 warp/node

    k_zero<<<(N_NODES + 255) / 256, 256>>>(1);
    k_deg4<<<(EQ4 + 255) / 256, 256>>>(1, (const int4*)esrc, (const int4*)edst);
    k_scan<<<SCAN_NB, SCAN_B>>>(1, gids);
    k_fillprep<<<FB + PB, 256>>>(1, (const int4*)esrc, (const int4*)edst, x);

    // layer 1: h1s(fp16) = relu(rin*gather(half(x*rout)) @ W1 + b1) * rout
    k_agg1h<<<AB, 256>>>(1);
    k_gemm_h<IN_DIM, true><<<GB, 256, gemm_smem_bytes(IN_DIM)>>>(1, W1, b1, nullptr);

    // layer 2: gather + GEMM + fused mean-pool numerator (h2 never hits gmem)
    k_agg2h<<<AB, 256>>>(1);
    k_gemm_h<HID, false><<<GB, 256, gemm_smem_bytes(HID)>>>(1, W2, b2, gids);

    // MLP head
    k_head<<<N_GRAPHS, HID>>>(1, Wc1, bc1, Wc2, bc2, Wc3, bc3, out);
}

// round 17
// speedup vs baseline: 1.0942x; 1.0028x over previous
#include <cuda_runtime.h>
#include <cuda_fp16.h>
#include <mma.h>

using namespace nvcuda;

#define N_NODES  100000
#define N_EDGES  1600000
#define N_GRAPHS 512
#define IN_DIM   64
#define HID      128

#define SCAN_B   1024
#define SCAN_NB  ((N_NODES + SCAN_B - 1) / SCAN_B)   // 98
#define EQ4      (N_EDGES / 4)                        // 400000 int4 quads
#define FB       ((EQ4 + 255) / 256)                  // 1563 fill blocks
#define PB       ((N_NODES * (IN_DIM / 2)) / 256)     // 12500 prep blocks

// GEMM smem sizing (whole-K resident): BM=64, BN=128, BK=K
constexpr int gemm_smem_bytes(int K) {
    int ALD = K + 8, WLDH = 128 + 8, CLD = 128 + 4;
    int ab = (64 * ALD + 2 * K * WLDH) * 2;
    int c  = 64 * CLD * 4;
    return ab > c ? ab : c;
}

// ---------------- device scratch ----------------
// RULE (R3/R6): referenced ONLY inside device code; never passed as kernel
// arguments from host (host shadow address + HMM = silent corruption or
// memory-guard trips).
__device__ int    g_deg_in[N_NODES];
__device__ int    g_deg_out[N_NODES];
__device__ int    g_row_ptr[N_NODES];
__device__ int    g_cursor[N_NODES];
__device__ int    g_csr_src[N_EDGES];
__device__ float  g_rin[N_NODES];
__device__ float  g_rout[N_NODES];
__device__ __half g_xh[(size_t)N_NODES * IN_DIM];   // half(x * rout)
__device__ __half g_h1h[(size_t)N_NODES * HID];     // half(h1s)
__device__ __half g_aggh[(size_t)N_NODES * HID];    // half(agg) - GEMM A operand
__device__ float  g_pool[N_GRAPHS * HID];
__device__ int    g_gcnt[N_GRAPHS];
// single-pass scan state (re-zeroed by k_zero each call)
__device__ volatile int g_ssum[SCAN_NB];
__device__ volatile int g_sflag[SCAN_NB];

// go=0: degenerate warmup launch (forces lazy function load, touches nothing).

__global__ void k_zero(int go) {
    if (!go) return;
    int i = blockIdx.x * blockDim.x + threadIdx.x;
    if (i < N_NODES) { g_deg_in[i] = 0; g_deg_out[i] = 0; }
    if (i < N_GRAPHS * HID) g_pool[i] = 0.f;
    if (i < N_GRAPHS) g_gcnt[i] = 0;
    if (i < SCAN_NB) { g_sflag[i] = 0; g_ssum[i] = 0; }
}

// degree count, 4 edges per thread (int4 loads)
__global__ void k_deg4(int go, const int4* __restrict__ src4, const int4* __restrict__ dst4) {
    if (!go) return;
    int q = blockIdx.x * blockDim.x + threadIdx.x;
    if (q >= EQ4) return;
    int4 s = src4[q];
    int4 d = dst4[q];
    atomicAdd(&g_deg_out[s.x], 1); atomicAdd(&g_deg_out[s.y], 1);
    atomicAdd(&g_deg_out[s.z], 1); atomicAdd(&g_deg_out[s.w], 1);
    atomicAdd(&g_deg_in[d.x], 1);  atomicAdd(&g_deg_in[d.y], 1);
    atomicAdd(&g_deg_in[d.z], 1);  atomicAdd(&g_deg_in[d.w], 1);
}

// single-pass scan + CSR pointers + norms. 98 co-resident blocks -> lookback safe.
__global__ void k_scan(int go, const int* __restrict__ gids) {
    if (!go) return;
    __shared__ int s[SCAN_B];
    __shared__ int s_prefix;
    int b = blockIdx.x;
    int i = b * SCAN_B + threadIdx.x;
    int v = (i < N_NODES) ? g_deg_in[i] : 0;
    s[threadIdx.x] = v;
    __syncthreads();
    for (int off = 1; off < SCAN_B; off <<= 1) {
        int t = (threadIdx.x >= off) ? s[threadIdx.x - off] : 0;
        __syncthreads();
        s[threadIdx.x] += t;
        __syncthreads();
    }
    int incl = s[threadIdx.x];
    if (threadIdx.x == SCAN_B - 1) {
        g_ssum[b] = s[SCAN_B - 1];
        __threadfence();
        g_sflag[b] = 1;
    }
    if (threadIdx.x < 32) {
        int acc = 0;
        for (int j = threadIdx.x; j < b; j += 32) {
            while (g_sflag[j] == 0) { }
            acc += g_ssum[j];
        }
#pragma unroll
        for (int o = 16; o > 0; o >>= 1)
            acc += __shfl_down_sync(0xffffffffu, acc, o);
        if (threadIdx.x == 0) s_prefix = acc;
    }
    __syncthreads();
    if (i < N_NODES) {
        int din = v;
        int rp = incl - din + s_prefix;
        g_row_ptr[i] = rp;
        g_cursor[i]  = rp;
        g_rin[i]  = rsqrtf((float)max(din, 1));
        g_rout[i] = rsqrtf((float)max(g_deg_out[i], 1));
        atomicAdd(&g_gcnt[gids[i]], 1);
    }
}

// fused: CSR bucket fill (4 edges/thread) + g_xh = half(x * rout)
__global__ void k_fillprep(int go, const int4* __restrict__ src4,
                           const int4* __restrict__ dst4,
                           const float* __restrict__ x) {
    if (!go) return;
    int b = blockIdx.x;
    if (b < FB) {
        int q = b * blockDim.x + threadIdx.x;
        if (q >= EQ4) return;
        int4 s = src4[q];
        int4 d = dst4[q];
        g_csr_src[atomicAdd(&g_cursor[d.x], 1)] = s.x;
        g_csr_src[atomicAdd(&g_cursor[d.y], 1)] = s.y;
        g_csr_src[atomicAdd(&g_cursor[d.z], 1)] = s.z;
        g_csr_src[atomicAdd(&g_cursor[d.w], 1)] = s.w;
    } else {
        int i = (b - FB) * blockDim.x + threadIdx.x;   // half2 slot over N*64
        if (i >= N_NODES * (IN_DIM / 2)) return;
        int node = i / (IN_DIM / 2);
        float r = g_rout[node];
        float2 v = ((const float2*)x)[i];
        ((__half2*)g_xh)[i] = __floats2half2_rn(v.x * r, v.y * r);
    }
}

// layer-1 gather: 2-way edge split, 16 dim-lanes x 4 halves (uint2)
__global__ void k_agg1h(int go) {
    if (!go) return;
    int warp = (blockIdx.x * blockDim.x + threadIdx.x) >> 5;
    if (warp >= N_NODES) return;
    int lane = threadIdx.x & 31;
    int sub = lane >> 4;          // 2 edges per iteration
    int dl  = lane & 15;          // 16 lanes x 4 halves = 64
    int start = g_row_ptr[warp];
    int deg   = g_deg_in[warp];
    float a0 = 0.f, a1 = 0.f, a2 = 0.f, a3 = 0.f;
#pragma unroll 4
    for (int e = sub; e < deg; e += 2) {
        int src = g_csr_src[start + e];
        uint2 u = *(const uint2*)(g_xh + (size_t)src * IN_DIM + dl * 4);
        float2 f0 = __half22float2(*(const __half2*)&u.x);
        float2 f1 = __half22float2(*(const __half2*)&u.y);
        a0 += f0.x; a1 += f0.y; a2 += f1.x; a3 += f1.y;
    }
    a0 += __shfl_down_sync(0xffffffffu, a0, 16);
    a1 += __shfl_down_sync(0xffffffffu, a1, 16);
    a2 += __shfl_down_sync(0xffffffffu, a2, 16);
    a3 += __shfl_down_sync(0xffffffffu, a3, 16);
    if (sub == 0) {
        float r = g_rin[warp];
        uint2 o;
        *(__half2*)&o.x = __floats2half2_rn(a0 * r, a1 * r);
        *(__half2*)&o.y = __floats2half2_rn(a2 * r, a3 * r);
        *(uint2*)(g_aggh + (size_t)warp * IN_DIM + dl * 4) = o;
    }
}

// layer-2 gather: 2-way edge split, 16 dim-lanes x 8 halves (uint4).
// Same bytes as the old 32-lane form, half the load instructions, 2 edges
// in flight per warp (mirrors the proven layer-1 shape).
__global__ void k_agg2h(int go) {
    if (!go) return;
    int warp = (blockIdx.x * blockDim.x + threadIdx.x) >> 5;
    if (warp >= N_NODES) return;
    int lane = threadIdx.x & 31;
    int sub = lane >> 4;          // 2 edges per iteration
    int dl  = lane & 15;          // 16 lanes x 8 halves = 128
    int start = g_row_ptr[warp];
    int deg   = g_deg_in[warp];
    float a[8];
#pragma unroll
    for (int k = 0; k < 8; k++) a[k] = 0.f;
#pragma unroll 4
    for (int e = sub; e < deg; e += 2) {
        int src = g_csr_src[start + e];
        uint4 u = *(const uint4*)(g_h1h + (size_t)src * HID + dl * 8);
        float2 f0 = __half22float2(*(const __half2*)&u.x);
        float2 f1 = __half22float2(*(const __half2*)&u.y);
        float2 f2 = __half22float2(*(const __half2*)&u.z);
        float2 f3 = __half22float2(*(const __half2*)&u.w);
        a[0] += f0.x; a[1] += f0.y; a[2] += f1.x; a[3] += f1.y;
        a[4] += f2.x; a[5] += f2.y; a[6] += f3.x; a[7] += f3.y;
    }
#pragma unroll
    for (int k = 0; k < 8; k++)
        a[k] += __shfl_down_sync(0xffffffffu, a[k], 16);
    if (sub == 0) {
        float r = g_rin[warp];
        uint4 o;
        *(__half2*)&o.x = __floats2half2_rn(a[0] * r, a[1] * r);
        *(__half2*)&o.y = __floats2half2_rn(a[2] * r, a[3] * r);
        *(__half2*)&o.z = __floats2half2_rn(a[4] * r, a[5] * r);
        *(__half2*)&o.w = __floats2half2_rn(a[6] * r, a[7] * r);
        *(uint4*)(g_aggh + (size_t)warp * HID + dl * 8) = o;
    }
}

// C = relu(g_aggh[M,K] @ W[K,128] + b), BM=64, whole-K resident (BK = K):
// single staging + single sync pair, then all MMAs run from resident smem.
// K=64: 44 KB smem; K=128: 87 KB (dynamic, opt-in set in EagerLoad).
// fp16 MMA (m16n16k16) with W split into Wh + Wl halves -> ~fp32 W precision.
// OUTH=true : *= rout, write fp16 to g_h1h  (layer 1)
// OUTH=false: pooled epilogue — accumulate relu rows into g_pool by gid
template<int K, bool OUTH>
__global__ __launch_bounds__(256) void k_gemm_h(int go,
                                                const float* __restrict__ W,
                                                const float* __restrict__ bias,
                                                const int* __restrict__ gids) {
    if (!go) return;
    constexpr int BM = 64, BN = 128, BK = K;
    constexpr int ALD  = BK + 8;   // halves
    constexpr int WLDH = BN + 8;   // halves
    constexpr int CLD  = BN + 4;   // floats
    extern __shared__ __align__(16) char smem_raw[];
    __half* Ah = (__half*)smem_raw;               // [BM][ALD]
    __half* Wh = Ah + BM * ALD;                   // [BK][WLDH]
    __half* Wl = Wh + BK * WLDH;                  // [BK][WLDH]
    float*  Cs = (float*)smem_raw;                // [BM][CLD] (epilogue)

    int tid = threadIdx.x;
    int warp = tid >> 5;
    int wm = warp >> 2;           // 0..1 (32 rows each)
    int wn = warp & 3;            // 0..3 (32 cols each)
    int m0 = blockIdx.x * BM;

    wmma::fragment<wmma::accumulator, 16, 16, 16, float> acc[2][2];
#pragma unroll
    for (int i = 0; i < 2; i++)
#pragma unroll
        for (int j = 0; j < 2; j++) wmma::fill_fragment(acc[i][j], 0.f);

    // A tile: BM x K halves, uint2 (4 halves) granularity — staged once
#pragma unroll
    for (int idx = tid; idx < BM * (BK / 4); idx += 256) {
        int row = idx / (BK / 4), c4 = idx % (BK / 4);
        int gm = m0 + row;
        uint2 v = make_uint2(0u, 0u);
        if (gm < N_NODES) v = *(const uint2*)(g_aggh + (size_t)gm * K + c4 * 4);
        *(uint2*)&Ah[row * ALD + c4 * 4] = v;
    }
    // W tile: K x 128 fp32 -> (Wh, Wl) halves; float4 granularity — staged once
#pragma unroll
    for (int idx = tid; idx < BK * 32; idx += 256) {
        int r = idx >> 5, c4 = idx & 31;
        float4 w = *(const float4*)(W + (size_t)r * BN + c4 * 4);
        __half2 h01 = __floats2half2_rn(w.x, w.y);
        __half2 h23 = __floats2half2_rn(w.z, w.w);
        float2 f01 = __half22float2(h01);
        float2 f23 = __half22float2(h23);
        __half2 l01 = __floats2half2_rn(w.x - f01.x, w.y - f01.y);
        __half2 l23 = __floats2half2_rn(w.z - f23.x, w.w - f23.y);
        uint2 hh, ll;
        *(__half2*)&hh.x = h01; *(__half2*)&hh.y = h23;
        *(__half2*)&ll.x = l01; *(__half2*)&ll.y = l23;
        *(uint2*)&Wh[r * WLDH + c4 * 4] = hh;
        *(uint2*)&Wl[r * WLDH + c4 * 4] = ll;
    }
    __syncthreads();

#pragma unroll
    for (int kk = 0; kk < BK; kk += 16) {
        wmma::fragment<wmma::matrix_a, 16, 16, 16, __half, wmma::row_major> a[2];
        wmma::fragment<wmma::matrix_b, 16, 16, 16, __half, wmma::row_major> bh[2], bl[2];
#pragma unroll
        for (int i = 0; i < 2; i++)
            wmma::load_matrix_sync(a[i], &Ah[(wm * 32 + i * 16) * ALD + kk], ALD);
#pragma unroll
        for (int j = 0; j < 2; j++) {
            wmma::load_matrix_sync(bh[j], &Wh[kk * WLDH + wn * 32 + j * 16], WLDH);
            wmma::load_matrix_sync(bl[j], &Wl[kk * WLDH + wn * 32 + j * 16], WLDH);
        }
#pragma unroll
        for (int i = 0; i < 2; i++)
#pragma unroll
            for (int j = 0; j < 2; j++) {
                wmma::mma_sync(acc[i][j], a[i], bh[j], acc[i][j]);
                wmma::mma_sync(acc[i][j], a[i], bl[j], acc[i][j]);
            }
    }
    __syncthreads();

#pragma unroll
    for (int i = 0; i < 2; i++)
#pragma unroll
        for (int j = 0; j < 2; j++)
            wmma::store_matrix_sync(&Cs[(wm * 32 + i * 16) * CLD + wn * 32 + j * 16],
                                    acc[i][j], CLD, wmma::mem_row_major);
    __syncthreads();

    if (OUTH) {
        // layer-1 epilogue: bias + relu, * rout, fp16 out
        int row = tid >> 2, seg = tid & 3;
        int gm = m0 + row;
        if (gm < N_NODES) {
            float r = g_rout[gm];
#pragma unroll
            for (int q = 0; q < 8; q++) {
                int col = seg * 32 + q * 4;
                float4 v = *(float4*)&Cs[row * CLD + col];
                uint2 u;
                *(__half2*)&u.x = __floats2half2_rn(fmaxf(v.x + bias[col + 0], 0.f) * r,
                                                    fmaxf(v.y + bias[col + 1], 0.f) * r);
                *(__half2*)&u.y = __floats2half2_rn(fmaxf(v.z + bias[col + 2], 0.f) * r,
                                                    fmaxf(v.w + bias[col + 3], 0.f) * r);
                *(uint2*)(g_h1h + (size_t)gm * BN + col) = u;
            }
        }
    } else {
        // layer-2 pooled epilogue: run-length accumulate by sorted gid
        int col = tid & 127;
        int r0 = (tid >> 7) * 32;
        float bcol = bias[col];
        int nrows = min(BM, N_NODES - m0);
        int lim = min(r0 + 32, nrows);
        if (r0 < nrows) {
            float acc_p = 0.f;
            int pg = gids[m0 + r0];
            for (int r = r0; r < lim; r++) {
                int g = gids[m0 + r];
                if (g != pg) {
                    atomicAdd(&g_pool[pg * HID + col], acc_p);
                    acc_p = 0.f;
                    pg = g;
                }
                acc_p += fmaxf(Cs[r * CLD + col] + bcol, 0.f);
            }
            atomicAdd(&g_pool[pg * HID + col], acc_p);
        }
    }
}

// MLP head: one block per graph
__global__ void k_head(int go,
                       const float* __restrict__ Wc1, const float* __restrict__ bc1,
                       const float* __restrict__ Wc2, const float* __restrict__ bc2,
                       const float* __restrict__ Wc3, const float* __restrict__ bc3,
                       float* __restrict__ out) {
    if (!go) return;
    __shared__ float s0[HID];
    __shared__ float s1[HID];
    int g = blockIdx.x, t = threadIdx.x;
    float cnt = fmaxf((float)g_gcnt[g], 1.f);
    s0[t] = g_pool[g * HID + t] / cnt;
    __syncthreads();
    float a = bc1[t];
#pragma unroll 8
    for (int k = 0; k < HID; k++) a = fmaf(s0[k], Wc1[k * HID + t], a);
    s1[t] = fmaxf(a, 0.f);
    __syncthreads();
    float b = bc2[t];
#pragma unroll 8
    for (int k = 0; k < HID; k++) b = fmaf(s1[k], Wc2[k * HID + t], b);
    float v = fmaxf(b, 0.f);
    __syncthreads();
    s1[t] = v * Wc3[t];
    __syncthreads();
    for (int off = 64; off > 0; off >>= 1) {
        if (t < off) s1[t] += s1[t + off];
        __syncthreads();
    }
    if (t == 0) out[g] = s1[0] + bc3[0];
}

// ---------------- eager module loader ----------------
namespace {
struct EagerLoad {
    EagerLoad() {
        int ndev = 0;
        if (cudaGetDeviceCount(&ndev) != cudaSuccess || ndev <= 0) return;
        for (int d = 0; d < ndev; d++) {
            if (cudaSetDevice(d) != cudaSuccess) continue;
            void* p;
            if (cudaGetSymbolAddress(&p, g_deg_in)  == cudaSuccess) cudaMemset(p, 0, sizeof(g_deg_in));
            if (cudaGetSymbolAddress(&p, g_deg_out) == cudaSuccess) cudaMemset(p, 0, sizeof(g_deg_out));
            if (cudaGetSymbolAddress(&p, g_row_ptr) == cudaSuccess) cudaMemset(p, 0, sizeof(g_row_ptr));
            if (cudaGetSymbolAddress(&p, g_cursor)  == cudaSuccess) cudaMemset(p, 0, sizeof(g_cursor));
            if (cudaGetSymbolAddress(&p, g_csr_src) == cudaSuccess) cudaMemset(p, 0, sizeof(g_csr_src));
            if (cudaGetSymbolAddress(&p, g_rin)     == cudaSuccess) cudaMemset(p, 0, sizeof(g_rin));
            if (cudaGetSymbolAddress(&p, g_rout)    == cudaSuccess) cudaMemset(p, 0, sizeof(g_rout));
            if (cudaGetSymbolAddress(&p, g_xh)      == cudaSuccess) cudaMemset(p, 0, sizeof(g_xh));
            if (cudaGetSymbolAddress(&p, g_h1h)     == cudaSuccess) cudaMemset(p, 0, sizeof(g_h1h));
            if (cudaGetSymbolAddress(&p, g_aggh)    == cudaSuccess) cudaMemset(p, 0, sizeof(g_aggh));
            if (cudaGetSymbolAddress(&p, g_pool)    == cudaSuccess) cudaMemset(p, 0, sizeof(g_pool));
            if (cudaGetSymbolAddress(&p, g_gcnt)    == cudaSuccess) cudaMemset(p, 0, sizeof(g_gcnt));
            if (cudaGetSymbolAddress(&p, (const void*)g_ssum)  == cudaSuccess) cudaMemset(p, 0, SCAN_NB * 4);
            if (cudaGetSymbolAddress(&p, (const void*)g_sflag) == cudaSuccess) cudaMemset(p, 0, SCAN_NB * 4);

            // opt-in to large dynamic smem for the whole-K GEMMs (attribute, not allocation)
            cudaFuncSetAttribute(k_gemm_h<IN_DIM, true>,
                                 cudaFuncAttributeMaxDynamicSharedMemorySize,
                                 gemm_smem_bytes(IN_DIM));
            cudaFuncSetAttribute(k_gemm_h<HID, false>,
                                 cudaFuncAttributeMaxDynamicSharedMemorySize,
                                 gemm_smem_bytes(HID));

            k_zero<<<1, 32>>>(0);
            k_deg4<<<1, 32>>>(0, nullptr, nullptr);
            k_scan<<<1, SCAN_B>>>(0, nullptr);
            k_fillprep<<<1, 256>>>(0, nullptr, nullptr, nullptr);
            k_agg1h<<<1, 128>>>(0);
            k_agg2h<<<1, 128>>>(0);
            k_gemm_h<IN_DIM, true><<<1, 256, gemm_smem_bytes(IN_DIM)>>>(0, nullptr, nullptr, nullptr);
            k_gemm_h<HID, false><<<1, 256, gemm_smem_bytes(HID)>>>(0, nullptr, nullptr, nullptr);
            k_head<<<1, HID>>>(0, nullptr, nullptr, nullptr, nullptr, nullptr, nullptr, nullptr);
            cudaDeviceSynchronize();
        }
        cudaSetDevice(0);
        cudaGetLastError();
    }
};
static EagerLoad _eager_load_instance;
}

// ---------------- launch ----------------
// Only harness-provided pointers cross the host/device argument boundary.
extern "C" void kernel_launch(void* const* d_in, const int* in_sizes, int n_in,
                              void* d_out, int out_size) {
    const float* x    = (const float*)d_in[0];
    const int*   esrc = (const int*)d_in[1];
    const int*   edst = (const int*)d_in[2];
    const int*   gids = (const int*)d_in[3];
    const float* W1 = (const float*)d_in[4];
    const float* b1 = (const float*)d_in[5];
    const float* W2 = (const float*)d_in[6];
    const float* b2 = (const float*)d_in[7];
    const float* Wc1 = (const float*)d_in[8];
    const float* bc1 = (const float*)d_in[9];
    const float* Wc2 = (const float*)d_in[10];
    const float* bc2 = (const float*)d_in[11];
    const float* Wc3 = (const float*)d_in[12];
    const float* bc3 = (const float*)d_in[13];
    float* out = (float*)d_out;

    const int GB = (N_NODES + 63) / 64;                // 1563 (BM=64)
    const int AB = (N_NODES * 32 + 127) / 128;         // 1 warp/node, 128-thr blocks

    k_zero<<<(N_NODES + 255) / 256, 256>>>(1);
    k_deg4<<<(EQ4 + 255) / 256, 256>>>(1, (const int4*)esrc, (const int4*)edst);
    k_scan<<<SCAN_NB, SCAN_B>>>(1, gids);
    k_fillprep<<<FB + PB, 256>>>(1, (const int4*)esrc, (const int4*)edst, x);

    // layer 1: h1s(fp16) = relu(rin*gather(half(x*rout)) @ W1 + b1) * rout
    k_agg1h<<<AB, 128>>>(1);
    k_gemm_h<IN_DIM, true><<<GB, 256, gemm_smem_bytes(IN_DIM)>>>(1, W1, b1, nullptr);

    // layer 2: gather + GEMM + fused mean-pool numerator (h2 never hits gmem)
    k_agg2h<<<AB, 128>>>(1);
    k_gemm_h<HID, false><<<GB, 256, gemm_smem_bytes(HID)>>>(1, W2, b2, gids);

    // MLP head
    k_head<<<N_GRAPHS, HID>>>(1, Wc1, bc1, Wc2, bc2, Wc3, bc3, out);
}